// round 4
// baseline (speedup 1.0000x reference)
#include <cuda_runtime.h>
#include <cstdint>
#include <cstddef>

// ---------------- problem constants ----------------
#define NN     16384      // nodes
#define DIN    1024
#define HH     4          // heads
#define CC     128        // channels/head
#define HC     512        // HH*CC
#define EE     262144     // edges (before self loops)
#define ETOT   (EE + NN)  // + self loops
#define BB     16
#define NODES  1024

// ---------------- device scratch (allocation-free rule: __device__ globals) ----------------
__device__ float    g_H[(size_t)NN * HC];     // transformed features (x@W)
__device__ float    g_O[(size_t)NN * HC];     // aggregation output / layer activations
__device__ float    g_as[NN * HH];
__device__ float    g_ad[NN * HH];
__device__ unsigned g_emax[NN * HH];          // order-encoded float max
__device__ float    g_denom[NN * HH];
__device__ float    g_ew[(size_t)ETOT * HH];  // per-edge exp weights
__device__ int      g_src[ETOT];
__device__ int      g_dst[ETOT];
__device__ int      g_is64;
__device__ float    g_x2[BB * NODES];
__device__ float    g_e1[BB * 512];
__device__ float    g_e2[BB * 256];
__device__ float    g_e3[BB * 128];
__device__ float    g_e4[BB * 64];

// ---------------- helpers ----------------
__device__ __forceinline__ float wsum(float v) {
#pragma unroll
    for (int o = 16; o > 0; o >>= 1) v += __shfl_xor_sync(0xffffffffu, v, o);
    return v;
}

// order-preserving encoding for atomicMax over floats
__device__ __forceinline__ unsigned fenc(float f) {
    unsigned u = __float_as_uint(f);
    return (u & 0x80000000u) ? ~u : (u | 0x80000000u);
}
__device__ __forceinline__ float fdec(unsigned u) {
    return (u & 0x80000000u) ? __uint_as_float(u & 0x7FFFFFFFu) : __uint_as_float(~u);
}

__device__ __forceinline__ void red4(float* p, float x, float y, float z, float w) {
    asm volatile("red.global.add.v4.f32 [%0], {%1,%2,%3,%4};"
                 :: "l"(p), "f"(x), "f"(y), "f"(z), "f"(w) : "memory");
}

// ---------------- edge index dtype detection + unpack ----------------
// If the buffer holds int64 values < 2^31, every odd 32-bit word is 0.
__global__ void detect_kernel(const int* __restrict__ buf) {
    __shared__ int sh[256];
    int v = 0;
    for (int i = threadIdx.x; i < 8192; i += 256) v |= buf[2 * i + 1];
    sh[threadIdx.x] = v;
    __syncthreads();
    for (int s = 128; s > 0; s >>= 1) {
        if (threadIdx.x < s) sh[threadIdx.x] |= sh[threadIdx.x + s];
        __syncthreads();
    }
    if (threadIdx.x == 0) g_is64 = (sh[0] == 0) ? 1 : 0;
}

__global__ void convert_kernel(const int* __restrict__ buf) {
    const int e = blockIdx.x * blockDim.x + threadIdx.x;
    if (e >= ETOT) return;
    if (e >= EE) { g_src[e] = e - EE; g_dst[e] = e - EE; return; }
    if (g_is64) {
        g_src[e] = buf[2 * e];
        g_dst[e] = buf[2 * (EE + e)];
    } else {
        g_src[e] = buf[e];
        g_dst[e] = buf[EE + e];
    }
}

// ---------------- SGEMM: C[M,N] = A[M,K] @ B[K,N], 128x128x8 tile, 256 thr, double-buffered ----------------
__global__ __launch_bounds__(256)
void sgemm128(const float* __restrict__ A, const float* __restrict__ B,
              float* __restrict__ C, int M, int N, int K) {
    __shared__ float As[2][8][128];
    __shared__ float Bs[2][8][128];
    const int tid   = threadIdx.x;
    const int mBase = blockIdx.y * 128;
    const int nBase = blockIdx.x * 128;

    const int a_r = tid >> 1, a_c = (tid & 1) * 4;
    const int b_r = tid >> 5, b_c = (tid & 31) * 4;

    const float* Aptr = A + (size_t)(mBase + a_r) * K + a_c;
    const float* Bptr = B + (size_t)b_r * N + nBase + b_c;

    float4 a4 = *(const float4*)Aptr;
    float4 b4 = *(const float4*)Bptr;
    As[0][a_c + 0][a_r] = a4.x; As[0][a_c + 1][a_r] = a4.y;
    As[0][a_c + 2][a_r] = a4.z; As[0][a_c + 3][a_r] = a4.w;
    *(float4*)&Bs[0][b_r][b_c] = b4;
    __syncthreads();

    const int tx = (tid & 15) * 4;
    const int ty = (tid >> 4) * 4;
    float acc[8][8];
#pragma unroll
    for (int i = 0; i < 8; i++)
#pragma unroll
        for (int j = 0; j < 8; j++) acc[i][j] = 0.f;

    const int nk = K >> 3;
    for (int kt = 0; kt < nk; kt++) {
        const int buf = kt & 1;
        if (kt + 1 < nk) {
            a4 = *(const float4*)(Aptr + (size_t)(kt + 1) * 8);
            b4 = *(const float4*)(Bptr + (size_t)(kt + 1) * 8 * N);
        }
#pragma unroll
        for (int k = 0; k < 8; k++) {
            float ar[8], br[8];
            *(float4*)&ar[0] = *(float4*)&As[buf][k][ty];
            *(float4*)&ar[4] = *(float4*)&As[buf][k][ty + 64];
            *(float4*)&br[0] = *(float4*)&Bs[buf][k][tx];
            *(float4*)&br[4] = *(float4*)&Bs[buf][k][tx + 64];
#pragma unroll
            for (int i = 0; i < 8; i++)
#pragma unroll
                for (int j = 0; j < 8; j++) acc[i][j] += ar[i] * br[j];
        }
        if (kt + 1 < nk) {
            const int nb = buf ^ 1;
            As[nb][a_c + 0][a_r] = a4.x; As[nb][a_c + 1][a_r] = a4.y;
            As[nb][a_c + 2][a_r] = a4.z; As[nb][a_c + 3][a_r] = a4.w;
            *(float4*)&Bs[nb][b_r][b_c] = b4;
        }
        __syncthreads();
    }

#pragma unroll
    for (int i = 0; i < 8; i++) {
        const int row = mBase + ((i < 4) ? (ty + i) : (64 + ty + i - 4));
        float* crow = C + (size_t)row * N + nBase;
        *(float4*)&crow[tx]      = make_float4(acc[i][0], acc[i][1], acc[i][2], acc[i][3]);
        *(float4*)&crow[tx + 64] = make_float4(acc[i][4], acc[i][5], acc[i][6], acc[i][7]);
    }
}

// ---------------- per-layer init: zero g_O, g_emax, g_denom ----------------
__global__ void init_layer() {
    const int i = blockIdx.x * blockDim.x + threadIdx.x;  // NN*HC/4 threads
    ((float4*)g_O)[i] = make_float4(0.f, 0.f, 0.f, 0.f);
    if (i < NN * HH) { g_emax[i] = 0u; g_denom[i] = 0.f; }
}

// ---------------- attention coefficients: as/ad[n,h] = <H[n,h,:], att[h,:]> ----------------
__global__ void alphas_kernel(const float* __restrict__ asrc, const float* __restrict__ adst) {
    const int n = blockIdx.x;
    const int h = threadIdx.x >> 5, lane = threadIdx.x & 31;
    const float4 hv = *(const float4*)&g_H[(size_t)n * HC + h * CC + lane * 4];
    const float4 s4 = *(const float4*)&asrc[h * CC + lane * 4];
    const float4 d4 = *(const float4*)&adst[h * CC + lane * 4];
    float ss = hv.x * s4.x + hv.y * s4.y + hv.z * s4.z + hv.w * s4.w;
    float sd = hv.x * d4.x + hv.y * d4.y + hv.z * d4.z + hv.w * d4.w;
    ss = wsum(ss); sd = wsum(sd);
    if (lane == 0) { g_as[n * HH + h] = ss; g_ad[n * HH + h] = sd; }
}

// ---------------- edge pass A: segment max (atomicMax on encoded float) ----------------
__global__ void edge_max() {
    const int e = blockIdx.x * blockDim.x + threadIdx.x;
    if (e >= ETOT) return;
    const int s = g_src[e], d = g_dst[e];
    const float4 a = *(const float4*)&g_as[s * HH];
    const float4 b = *(const float4*)&g_ad[d * HH];
    float v[4] = {a.x + b.x, a.y + b.y, a.z + b.z, a.w + b.w};
#pragma unroll
    for (int h = 0; h < 4; h++) {
        float x = v[h]; x = (x > 0.f) ? x : 0.2f * x;  // leaky_relu 0.2
        atomicMax(&g_emax[d * HH + h], fenc(x));
    }
}

// ---------------- edge pass B: exp + segment sum; cache per-edge exp ----------------
__global__ void edge_expsum() {
    const int e = blockIdx.x * blockDim.x + threadIdx.x;
    if (e >= ETOT) return;
    const int s = g_src[e], d = g_dst[e];
    const float4 a = *(const float4*)&g_as[s * HH];
    const float4 b = *(const float4*)&g_ad[d * HH];
    float v[4] = {a.x + b.x, a.y + b.y, a.z + b.z, a.w + b.w};
    float ex[4];
#pragma unroll
    for (int h = 0; h < 4; h++) {
        float x = v[h]; x = (x > 0.f) ? x : 0.2f * x;
        const float m = fdec(g_emax[d * HH + h]);
        ex[h] = __expf(x - m);
        atomicAdd(&g_denom[d * HH + h], ex[h]);
    }
    *(float4*)&g_ew[(size_t)e * HH] = make_float4(ex[0], ex[1], ex[2], ex[3]);
}

// ---------------- edge pass C: aggregate messages (warp/edge, v4 global reductions) ----------------
__global__ void edge_aggregate() {
    const int e    = (blockIdx.x * blockDim.x + threadIdx.x) >> 5;
    const int lane = threadIdx.x & 31;
    if (e >= ETOT) return;
    const int s = g_src[e], d = g_dst[e];
    const float4 w4 = *(const float4*)&g_ew[(size_t)e * HH];
    const float4 dn = *(const float4*)&g_denom[d * HH];
    const float al[4] = {w4.x / (dn.x + 1e-16f), w4.y / (dn.y + 1e-16f),
                         w4.z / (dn.z + 1e-16f), w4.w / (dn.w + 1e-16f)};
    const float4* hp = (const float4*)&g_H[(size_t)s * HC];
    float* op = &g_O[(size_t)d * HC];
#pragma unroll
    for (int h = 0; h < 4; h++) {
        const float4 v = hp[h * 32 + lane];
        const float a = al[h];
        red4(&op[h * CC + lane * 4], v.x * a, v.y * a, v.z * a, v.w * a);
    }
}

// ---------------- bias + ELU (in place on g_O) ----------------
__global__ void bias_elu(const float* __restrict__ bias) {
    const size_t i = (size_t)blockIdx.x * blockDim.x + threadIdx.x;  // NN*HC threads
    const float v = g_O[i] + bias[i & (HC - 1)];
    g_O[i] = (v > 0.f) ? v : expm1f(v);
}

// ---------------- pool2: x2[n] = <h2[n,:], p2w> + p2b ----------------
__global__ void pool2_kernel(const float* __restrict__ w, const float* __restrict__ b) {
    const int n    = (blockIdx.x * blockDim.x + threadIdx.x) >> 5;
    const int lane = threadIdx.x & 31;
    if (n >= NN) return;
    const float4* hp = (const float4*)&g_O[(size_t)n * HC];
    const float4* wp = (const float4*)w;
    float s = 0.f;
#pragma unroll
    for (int p = 0; p < 4; p++) {
        const float4 v = hp[p * 32 + lane];
        const float4 ww = wp[p * 32 + lane];
        s += v.x * ww.x + v.y * ww.y + v.z * ww.z + v.w * ww.w;
    }
    s = wsum(s);
    if (lane == 0) g_x2[n] = s + b[0];
}

// ---------------- layer norm over each batch row of 1024; writes d_out[0:16384) and g_x2 ----------------
__global__ void ln_kernel(const float* __restrict__ g, const float* __restrict__ be,
                          float* __restrict__ out) {
    const int bb = blockIdx.x, tid = threadIdx.x;
    const int lane = tid & 31, wid = tid >> 5;
    float s = 0.f, s2 = 0.f;
    for (int i = tid; i < NODES; i += 256) {
        const float v = g_x2[bb * NODES + i];
        s += v; s2 += v * v;
    }
    s = wsum(s); s2 = wsum(s2);
    __shared__ float shs[8], shs2[8];
    if (lane == 0) { shs[wid] = s; shs2[wid] = s2; }
    __syncthreads();
    __shared__ float smu, srv;
    if (tid == 0) {
        float S = 0.f, S2 = 0.f;
        for (int w = 0; w < 8; w++) { S += shs[w]; S2 += shs2[w]; }
        const float mu = S / NODES;
        smu = mu;
        srv = rsqrtf(S2 / NODES - mu * mu + 1e-5f);
    }
    __syncthreads();
    const float mu = smu, rv = srv;
    for (int i = tid; i < NODES; i += 256) {
        const float v = (g_x2[bb * NODES + i] - mu) * rv * g[i] + be[i];
        out[bb * NODES + i] = v;
        g_x2[bb * NODES + i] = v;
    }
}

// ---------------- small FC: out[b,j] = act(in[b,:] @ W[:,j] + bias[j]) ----------------
__global__ void fc_kernel(const float* __restrict__ in, const float* __restrict__ W,
                          const float* __restrict__ bias, float* __restrict__ out,
                          int Din, int Dout, int act) {
    const int j = blockIdx.x * blockDim.x + threadIdx.x;
    const int b = blockIdx.y;
    if (j >= Dout) return;
    const float* ir = in + (size_t)b * Din;
    float s = bias[j];
    for (int k = 0; k < Din; k++) s += ir[k] * W[(size_t)k * Dout + j];
    if (act) s = (s > 0.f) ? s : expm1f(s);
    out[b * Dout + j] = s;
}

// ---------------- final: write e[16,64] and pred[16] to d_out ----------------
__global__ void final_kernel(const float* __restrict__ lw, const float* __restrict__ lb,
                             float* __restrict__ out) {
    const int b = blockIdx.x, tid = threadIdx.x;  // 64 threads
    const float v = g_e4[b * 64 + tid];
    out[BB * NODES + b * 64 + tid] = v;
    float p = v * lw[tid];
#pragma unroll
    for (int o = 16; o > 0; o >>= 1) p += __shfl_xor_sync(0xffffffffu, p, o);
    __shared__ float sh[2];
    if ((tid & 31) == 0) sh[tid >> 5] = p;
    __syncthreads();
    if (tid == 0) out[BB * NODES + BB * 64 + b] = sh[0] + sh[1] + lb[0];
}

// ---------------- launch ----------------
extern "C" void kernel_launch(void* const* d_in, const int* in_sizes, int n_in,
                              void* d_out, int out_size) {
    const float* x    = (const float*)d_in[0];
    const int*   eibuf= (const int*)d_in[1];   // int32 OR int64 (detected on device)
    // d_in[2] = batch (unused; structure is known)
    const float* W1   = (const float*)d_in[3];
    const float* as1  = (const float*)d_in[4];
    const float* ad1  = (const float*)d_in[5];
    const float* b1   = (const float*)d_in[6];
    const float* W2   = (const float*)d_in[7];
    const float* as2  = (const float*)d_in[8];
    const float* ad2  = (const float*)d_in[9];
    const float* b2   = (const float*)d_in[10];
    // d_in[11], d_in[12] = p1w/p1b : dead in the reference graph
    const float* p2w  = (const float*)d_in[13];
    const float* p2b  = (const float*)d_in[14];
    const float* ln_g = (const float*)d_in[15];
    const float* ln_b = (const float*)d_in[16];
    const float* fw1  = (const float*)d_in[17];
    const float* fb1  = (const float*)d_in[18];
    const float* fw2  = (const float*)d_in[19];
    const float* fb2  = (const float*)d_in[20];
    const float* fw3  = (const float*)d_in[21];
    const float* fb3  = (const float*)d_in[22];
    const float* fw4  = (const float*)d_in[23];
    const float* fb4  = (const float*)d_in[24];
    const float* lw   = (const float*)d_in[25];
    const float* lb   = (const float*)d_in[26];
    float* out = (float*)d_out;

    float *pH, *pO, *px2, *pe1, *pe2, *pe3, *pe4;
    cudaGetSymbolAddress((void**)&pH,  g_H);
    cudaGetSymbolAddress((void**)&pO,  g_O);
    cudaGetSymbolAddress((void**)&px2, g_x2);
    cudaGetSymbolAddress((void**)&pe1, g_e1);
    cudaGetSymbolAddress((void**)&pe2, g_e2);
    cudaGetSymbolAddress((void**)&pe3, g_e3);
    cudaGetSymbolAddress((void**)&pe4, g_e4);

    const int eblocks = (ETOT + 255) / 256;          // thread-per-edge passes
    const int ablocks = (ETOT * 32 + 255) / 256;     // warp-per-edge aggregate
    const dim3 gemm_grid(HC / 128, NN / 128);

    // ===== edge-index dtype detect + unpack =====
    detect_kernel<<<1, 256>>>(eibuf);
    convert_kernel<<<eblocks, 256>>>(eibuf);

    // ===== GAT layer 1 =====
    sgemm128<<<gemm_grid, 256>>>(x, W1, pH, NN, HC, DIN);
    alphas_kernel<<<NN, 128>>>(as1, ad1);
    init_layer<<<(NN * HC / 4) / 256, 256>>>();
    edge_max<<<eblocks, 256>>>();
    edge_expsum<<<eblocks, 256>>>();
    edge_aggregate<<<ablocks, 256>>>();
    bias_elu<<<(NN * HC) / 256, 256>>>(b1);          // g_O = h1

    // ===== GAT layer 2 =====
    sgemm128<<<gemm_grid, 256>>>(pO, W2, pH, NN, HC, HC);
    alphas_kernel<<<NN, 128>>>(as2, ad2);
    init_layer<<<(NN * HC / 4) / 256, 256>>>();
    edge_max<<<eblocks, 256>>>();
    edge_expsum<<<eblocks, 256>>>();
    edge_aggregate<<<ablocks, 256>>>();
    bias_elu<<<(NN * HC) / 256, 256>>>(b2);          // g_O = h2

    // ===== pooling + layer norm (multiscale -> d_out[0:16384)) =====
    pool2_kernel<<<(NN * 32) / 256, 256>>>(p2w, p2b);
    ln_kernel<<<BB, 256>>>(ln_g, ln_b, out);

    // ===== encoder MLP =====
    fc_kernel<<<dim3(4, BB), 128>>>(px2, fw1, fb1, pe1, 1024, 512, 1);
    fc_kernel<<<dim3(2, BB), 128>>>(pe1, fw2, fb2, pe2, 512, 256, 1);
    fc_kernel<<<dim3(1, BB), 128>>>(pe2, fw3, fb3, pe3, 256, 128, 1);
    fc_kernel<<<dim3(1, BB), 128>>>(pe3, fw4, fb4, pe4, 128, 64, 1);
    final_kernel<<<BB, 64>>>(lw, lb, out);
}

// round 5
// speedup vs baseline: 1.4046x; 1.4046x over previous
#include <cuda_runtime.h>
#include <cuda_bf16.h>
#include <cstdint>
#include <cstddef>

// ---------------- problem constants ----------------
#define NN     16384      // nodes
#define DIN    1024
#define HH     4          // heads
#define CC     128        // channels/head
#define HC     512        // HH*CC
#define EE     262144     // edges (before self loops)
#define ETOT   (EE + NN)  // + self loops
#define BB     16
#define NODES  1024

// ---------------- device scratch ----------------
__device__ float         g_H[(size_t)NN * HC];     // transformed features (x@W)
__device__ float         g_O[(size_t)NN * HC];     // aggregation output / layer activations
__device__ __nv_bfloat16 g_Ahi[(size_t)NN * DIN];
__device__ __nv_bfloat16 g_Alo[(size_t)NN * DIN];
__device__ __nv_bfloat16 g_Bhi[DIN * HC];
__device__ __nv_bfloat16 g_Blo[DIN * HC];
__device__ float         g_as[NN * HH];
__device__ float         g_ad[NN * HH];
__device__ unsigned      g_emax[NN * HH];          // order-encoded float max
__device__ float         g_denom[NN * HH];
__device__ float         g_ew[(size_t)ETOT * HH];  // per-edge exp weights
__device__ int           g_src[ETOT];
__device__ int           g_dst[ETOT];
__device__ int           g_is64;
__device__ float         g_x2[BB * NODES];
__device__ float         g_e1[BB * 512];
__device__ float         g_e2[BB * 256];
__device__ float         g_e3[BB * 128];
__device__ float         g_e4[BB * 64];

// ---------------- helpers ----------------
__device__ __forceinline__ float wsum(float v) {
#pragma unroll
    for (int o = 16; o > 0; o >>= 1) v += __shfl_xor_sync(0xffffffffu, v, o);
    return v;
}
__device__ __forceinline__ unsigned fenc(float f) {
    unsigned u = __float_as_uint(f);
    return (u & 0x80000000u) ? ~u : (u | 0x80000000u);
}
__device__ __forceinline__ float fdec(unsigned u) {
    return (u & 0x80000000u) ? __uint_as_float(u & 0x7FFFFFFFu) : __uint_as_float(~u);
}
__device__ __forceinline__ void red4(float* p, float x, float y, float z, float w) {
    asm volatile("red.global.add.v4.f32 [%0], {%1,%2,%3,%4};"
                 :: "l"(p), "f"(x), "f"(y), "f"(z), "f"(w) : "memory");
}
__device__ __forceinline__ void cp16(unsigned s, const void* g) {
    asm volatile("cp.async.cg.shared.global [%0], [%1], 16;" :: "r"(s), "l"(g));
}
__device__ __forceinline__ void ldsm4(unsigned* r, unsigned a) {
    asm volatile("ldmatrix.sync.aligned.m8n8.x4.shared.b16 {%0,%1,%2,%3}, [%4];"
                 : "=r"(r[0]), "=r"(r[1]), "=r"(r[2]), "=r"(r[3]) : "r"(a));
}
__device__ __forceinline__ void ldsm4t(unsigned* r, unsigned a) {
    asm volatile("ldmatrix.sync.aligned.m8n8.x4.trans.shared.b16 {%0,%1,%2,%3}, [%4];"
                 : "=r"(r[0]), "=r"(r[1]), "=r"(r[2]), "=r"(r[3]) : "r"(a));
}
__device__ __forceinline__ void mma16816(float* c, const unsigned* a, const unsigned* b) {
    asm volatile("mma.sync.aligned.m16n8k16.row.col.f32.bf16.bf16.f32 "
                 "{%0,%1,%2,%3}, {%4,%5,%6,%7}, {%8,%9}, {%0,%1,%2,%3};"
                 : "+f"(c[0]), "+f"(c[1]), "+f"(c[2]), "+f"(c[3])
                 : "r"(a[0]), "r"(a[1]), "r"(a[2]), "r"(a[3]), "r"(b[0]), "r"(b[1]));
}

// ---------------- fp32 -> bf16 hi/lo split ----------------
__global__ void split_kernel(const float* __restrict__ x, __nv_bfloat16* __restrict__ hi,
                             __nv_bfloat16* __restrict__ lo) {
    const size_t i = (size_t)blockIdx.x * blockDim.x + threadIdx.x;  // float4 index
    const float4 v = ((const float4*)x)[i];
    const __nv_bfloat16 h0 = __float2bfloat16(v.x), h1 = __float2bfloat16(v.y);
    const __nv_bfloat16 h2 = __float2bfloat16(v.z), h3 = __float2bfloat16(v.w);
    const __nv_bfloat16 l0 = __float2bfloat16(v.x - __bfloat162float(h0));
    const __nv_bfloat16 l1 = __float2bfloat16(v.y - __bfloat162float(h1));
    const __nv_bfloat16 l2 = __float2bfloat16(v.z - __bfloat162float(h2));
    const __nv_bfloat16 l3 = __float2bfloat16(v.w - __bfloat162float(h3));
    __nv_bfloat162* hp = (__nv_bfloat162*)hi;
    __nv_bfloat162* lp = (__nv_bfloat162*)lo;
    hp[2 * i]     = __halves2bfloat162(h0, h1);
    hp[2 * i + 1] = __halves2bfloat162(h2, h3);
    lp[2 * i]     = __halves2bfloat162(l0, l1);
    lp[2 * i + 1] = __halves2bfloat162(l2, l3);
}

// ---------------- bf16-split tensor GEMM: C = Ahi*Bhi + Ahi*Blo + Alo*Bhi ----------------
// CTA tile 128x128x32, 8 warps (4x2, each 32x64), double-buffered cp.async, swizzled smem.
// smem layout (bf16 elements): A: [stage*2+split][4096] at 0 ; B: same at 16384.
__global__ __launch_bounds__(256)
void gemm_bf16split(const __nv_bfloat16* __restrict__ Ahi, const __nv_bfloat16* __restrict__ Alo,
                    const __nv_bfloat16* __restrict__ Bhi, const __nv_bfloat16* __restrict__ Blo,
                    float* __restrict__ C, int M, int N, int K) {
    extern __shared__ __nv_bfloat16 sm[];
    const int tid   = threadIdx.x;
    const int mBase = blockIdx.y * 128;
    const int nBase = blockIdx.x * 128;
    const unsigned sbase = (unsigned)__cvta_generic_to_shared(sm);

    const int wid = tid >> 5, lane = tid & 31;
    const int wm = wid & 3;       // 4 m-warps of 32 rows
    const int wn = wid >> 2;      // 2 n-warps of 64 cols

    float acc[2][8][4];
#pragma unroll
    for (int i = 0; i < 2; i++)
#pragma unroll
        for (int j = 0; j < 8; j++)
#pragma unroll
            for (int k = 0; k < 4; k++) acc[i][j][k] = 0.f;

    auto load_stage = [&](int stage, int kt) {
        const int kb = kt * 32;
        // A tiles: 128x32 bf16 per split, 512 16B-chunks per split
#pragma unroll
        for (int i = 0; i < 2; i++) {
            const int chunk = tid + (i << 8);
            const int row = chunk >> 2, u = chunk & 3;
            const int su = u ^ ((row >> 1) & 3);
            const size_t goff = (size_t)(mBase + row) * K + kb + u * 8;
            const unsigned s0 = sbase + (unsigned)((stage * 2) * 4096 + row * 32 + su * 8) * 2;
            cp16(s0,            Ahi + goff);
            cp16(s0 + 4096 * 2, Alo + goff);
        }
        // B tiles: 32x128 bf16 per split
#pragma unroll
        for (int i = 0; i < 2; i++) {
            const int chunk = tid + (i << 8);
            const int row = chunk >> 4, u = chunk & 15;
            const int su = u ^ (row & 7);
            const size_t goff = (size_t)(kb + row) * N + nBase + u * 8;
            const unsigned s0 = sbase + (unsigned)(16384 + (stage * 2) * 4096 + row * 128 + su * 8) * 2;
            cp16(s0,            Bhi + goff);
            cp16(s0 + 4096 * 2, Blo + goff);
        }
    };

    const int nk = K >> 5;
    load_stage(0, 0);
    asm volatile("cp.async.commit_group;");

    for (int kt = 0; kt < nk; kt++) {
        if (kt + 1 < nk) load_stage((kt + 1) & 1, kt + 1);
        asm volatile("cp.async.commit_group;");
        asm volatile("cp.async.wait_group 1;");
        __syncthreads();

        const int stage = kt & 1;
        const unsigned aStage = sbase + (unsigned)((stage * 2) * 4096) * 2;
        const unsigned bStage = sbase + (unsigned)(16384 + (stage * 2) * 4096) * 2;
#pragma unroll
        for (int kk = 0; kk < 2; kk++) {
            unsigned ah[2][4], al[2][4], bh[4][4], bl[4][4];
#pragma unroll
            for (int mt = 0; mt < 2; mt++) {
                const int row = wm * 32 + mt * 16 + (lane & 15);
                const int u = (kk * 2 + (lane >> 4)) ^ ((row >> 1) & 3);
                const unsigned ad = aStage + (unsigned)(row * 32 + u * 8) * 2;
                ldsm4(ah[mt], ad);
                ldsm4(al[mt], ad + 4096 * 2);
            }
#pragma unroll
            for (int nt = 0; nt < 4; nt++) {
                const int row = kk * 16 + (lane & 15);
                const int u = (wn * 8 + nt * 2 + (lane >> 4)) ^ (row & 7);
                const unsigned bd = bStage + (unsigned)(row * 128 + u * 8) * 2;
                ldsm4t(bh[nt], bd);
                ldsm4t(bl[nt], bd + 4096 * 2);
            }
            // three products, interleaved over 16 independent accumulators
#pragma unroll
            for (int mt = 0; mt < 2; mt++)
#pragma unroll
                for (int n8 = 0; n8 < 8; n8++)
                    mma16816(acc[mt][n8], ah[mt], &bh[n8 >> 1][(n8 & 1) * 2]);
#pragma unroll
            for (int mt = 0; mt < 2; mt++)
#pragma unroll
                for (int n8 = 0; n8 < 8; n8++)
                    mma16816(acc[mt][n8], ah[mt], &bl[n8 >> 1][(n8 & 1) * 2]);
#pragma unroll
            for (int mt = 0; mt < 2; mt++)
#pragma unroll
                for (int n8 = 0; n8 < 8; n8++)
                    mma16816(acc[mt][n8], al[mt], &bh[n8 >> 1][(n8 & 1) * 2]);
        }
        __syncthreads();
    }

    // epilogue
#pragma unroll
    for (int mt = 0; mt < 2; mt++) {
#pragma unroll
        for (int n8 = 0; n8 < 8; n8++) {
            const int row0 = mBase + wm * 32 + mt * 16 + (lane >> 2);
            const int col  = nBase + wn * 64 + n8 * 8 + (lane & 3) * 2;
            *(float2*)&C[(size_t)row0 * N + col]       = make_float2(acc[mt][n8][0], acc[mt][n8][1]);
            *(float2*)&C[(size_t)(row0 + 8) * N + col] = make_float2(acc[mt][n8][2], acc[mt][n8][3]);
        }
    }
}

// ---------------- edge index dtype detection + unpack ----------------
__global__ void detect_kernel(const int* __restrict__ buf) {
    __shared__ int sh[256];
    int v = 0;
    for (int i = threadIdx.x; i < 8192; i += 256) v |= buf[2 * i + 1];
    sh[threadIdx.x] = v;
    __syncthreads();
    for (int s = 128; s > 0; s >>= 1) {
        if (threadIdx.x < s) sh[threadIdx.x] |= sh[threadIdx.x + s];
        __syncthreads();
    }
    if (threadIdx.x == 0) g_is64 = (sh[0] == 0) ? 1 : 0;
}

__global__ void convert_kernel(const int* __restrict__ buf) {
    const int e = blockIdx.x * blockDim.x + threadIdx.x;
    if (e >= ETOT) return;
    if (e >= EE) { g_src[e] = e - EE; g_dst[e] = e - EE; return; }
    if (g_is64) { g_src[e] = buf[2 * e]; g_dst[e] = buf[2 * (EE + e)]; }
    else        { g_src[e] = buf[e];     g_dst[e] = buf[EE + e]; }
}

// ---------------- per-layer init ----------------
__global__ void init_layer() {
    const int i = blockIdx.x * blockDim.x + threadIdx.x;
    ((float4*)g_O)[i] = make_float4(0.f, 0.f, 0.f, 0.f);
    if (i < NN * HH) { g_emax[i] = 0u; g_denom[i] = 0.f; }
}

// ---------------- attention coefficients ----------------
__global__ void alphas_kernel(const float* __restrict__ asrc, const float* __restrict__ adst) {
    const int n = blockIdx.x;
    const int h = threadIdx.x >> 5, lane = threadIdx.x & 31;
    const float4 hv = *(const float4*)&g_H[(size_t)n * HC + h * CC + lane * 4];
    const float4 s4 = *(const float4*)&asrc[h * CC + lane * 4];
    const float4 d4 = *(const float4*)&adst[h * CC + lane * 4];
    float ss = hv.x * s4.x + hv.y * s4.y + hv.z * s4.z + hv.w * s4.w;
    float sd = hv.x * d4.x + hv.y * d4.y + hv.z * d4.z + hv.w * d4.w;
    ss = wsum(ss); sd = wsum(sd);
    if (lane == 0) { g_as[n * HH + h] = ss; g_ad[n * HH + h] = sd; }
}

// ---------------- edge passes ----------------
__global__ void edge_max() {
    const int e = blockIdx.x * blockDim.x + threadIdx.x;
    if (e >= ETOT) return;
    const int s = g_src[e], d = g_dst[e];
    const float4 a = *(const float4*)&g_as[s * HH];
    const float4 b = *(const float4*)&g_ad[d * HH];
    float v[4] = {a.x + b.x, a.y + b.y, a.z + b.z, a.w + b.w};
#pragma unroll
    for (int h = 0; h < 4; h++) {
        float x = v[h]; x = (x > 0.f) ? x : 0.2f * x;
        atomicMax(&g_emax[d * HH + h], fenc(x));
    }
}

__global__ void edge_expsum() {
    const int e = blockIdx.x * blockDim.x + threadIdx.x;
    if (e >= ETOT) return;
    const int s = g_src[e], d = g_dst[e];
    const float4 a = *(const float4*)&g_as[s * HH];
    const float4 b = *(const float4*)&g_ad[d * HH];
    float v[4] = {a.x + b.x, a.y + b.y, a.z + b.z, a.w + b.w};
    float ex[4];
#pragma unroll
    for (int h = 0; h < 4; h++) {
        float x = v[h]; x = (x > 0.f) ? x : 0.2f * x;
        const float m = fdec(g_emax[d * HH + h]);
        ex[h] = __expf(x - m);
        atomicAdd(&g_denom[d * HH + h], ex[h]);
    }
    *(float4*)&g_ew[(size_t)e * HH] = make_float4(ex[0], ex[1], ex[2], ex[3]);
}

__global__ void edge_aggregate() {
    const int e    = (blockIdx.x * blockDim.x + threadIdx.x) >> 5;
    const int lane = threadIdx.x & 31;
    if (e >= ETOT) return;
    const int s = g_src[e], d = g_dst[e];
    const float4 w4 = *(const float4*)&g_ew[(size_t)e * HH];
    const float4 dn = *(const float4*)&g_denom[d * HH];
    const float al[4] = {w4.x / (dn.x + 1e-16f), w4.y / (dn.y + 1e-16f),
                         w4.z / (dn.z + 1e-16f), w4.w / (dn.w + 1e-16f)};
    const float4* hp = (const float4*)&g_H[(size_t)s * HC];
    float* op = &g_O[(size_t)d * HC];
#pragma unroll
    for (int h = 0; h < 4; h++) {
        const float4 v = hp[h * 32 + lane];
        const float a = al[h];
        red4(&op[h * CC + lane * 4], v.x * a, v.y * a, v.z * a, v.w * a);
    }
}

// ---------------- bias + ELU ----------------
__global__ void bias_elu(const float* __restrict__ bias) {
    const size_t i = (size_t)blockIdx.x * blockDim.x + threadIdx.x;
    const float v = g_O[i] + bias[i & (HC - 1)];
    g_O[i] = (v > 0.f) ? v : expm1f(v);
}

// ---------------- pool2 ----------------
__global__ void pool2_kernel(const float* __restrict__ w, const float* __restrict__ b) {
    const int n    = (blockIdx.x * blockDim.x + threadIdx.x) >> 5;
    const int lane = threadIdx.x & 31;
    if (n >= NN) return;
    const float4* hp = (const float4*)&g_O[(size_t)n * HC];
    const float4* wp = (const float4*)w;
    float s = 0.f;
#pragma unroll
    for (int p = 0; p < 4; p++) {
        const float4 v  = hp[p * 32 + lane];
        const float4 ww = wp[p * 32 + lane];
        s += v.x * ww.x + v.y * ww.y + v.z * ww.z + v.w * ww.w;
    }
    s = wsum(s);
    if (lane == 0) g_x2[n] = s + b[0];
}

// ---------------- layer norm ----------------
__global__ void ln_kernel(const float* __restrict__ g, const float* __restrict__ be,
                          float* __restrict__ out) {
    const int bb = blockIdx.x, tid = threadIdx.x;
    const int lane = tid & 31, wid = tid >> 5;
    float s = 0.f, s2 = 0.f;
    for (int i = tid; i < NODES; i += 256) {
        const float v = g_x2[bb * NODES + i];
        s += v; s2 += v * v;
    }
    s = wsum(s); s2 = wsum(s2);
    __shared__ float shs[8], shs2[8];
    if (lane == 0) { shs[wid] = s; shs2[wid] = s2; }
    __syncthreads();
    __shared__ float smu, srv;
    if (tid == 0) {
        float S = 0.f, S2 = 0.f;
        for (int w = 0; w < 8; w++) { S += shs[w]; S2 += shs2[w]; }
        const float mu = S / NODES;
        smu = mu;
        srv = rsqrtf(S2 / NODES - mu * mu + 1e-5f);
    }
    __syncthreads();
    const float mu = smu, rv = srv;
    for (int i = tid; i < NODES; i += 256) {
        const float v = (g_x2[bb * NODES + i] - mu) * rv * g[i] + be[i];
        out[bb * NODES + i] = v;
        g_x2[bb * NODES + i] = v;
    }
}

// ---------------- small FC ----------------
__global__ void fc_kernel(const float* __restrict__ in, const float* __restrict__ W,
                          const float* __restrict__ bias, float* __restrict__ out,
                          int Din, int Dout, int act) {
    const int j = blockIdx.x * blockDim.x + threadIdx.x;
    const int b = blockIdx.y;
    if (j >= Dout) return;
    const float* ir = in + (size_t)b * Din;
    float s = bias[j];
    for (int k = 0; k < Din; k++) s += ir[k] * W[(size_t)k * Dout + j];
    if (act) s = (s > 0.f) ? s : expm1f(s);
    out[b * Dout + j] = s;
}

// ---------------- final ----------------
__global__ void final_kernel(const float* __restrict__ lw, const float* __restrict__ lb,
                             float* __restrict__ out) {
    const int b = blockIdx.x, tid = threadIdx.x;  // 64 threads
    const float v = g_e4[b * 64 + tid];
    out[BB * NODES + b * 64 + tid] = v;
    float p = v * lw[tid];
#pragma unroll
    for (int o = 16; o > 0; o >>= 1) p += __shfl_xor_sync(0xffffffffu, p, o);
    __shared__ float sh[2];
    if ((tid & 31) == 0) sh[tid >> 5] = p;
    __syncthreads();
    if (tid == 0) out[BB * NODES + BB * 64 + b] = sh[0] + sh[1] + lb[0];
}

// ---------------- launch ----------------
extern "C" void kernel_launch(void* const* d_in, const int* in_sizes, int n_in,
                              void* d_out, int out_size) {
    const float* x     = (const float*)d_in[0];
    const int*   eibuf = (const int*)d_in[1];
    const float* W1   = (const float*)d_in[3];
    const float* as1  = (const float*)d_in[4];
    const float* ad1  = (const float*)d_in[5];
    const float* b1   = (const float*)d_in[6];
    const float* W2   = (const float*)d_in[7];
    const float* as2  = (const float*)d_in[8];
    const float* ad2  = (const float*)d_in[9];
    const float* b2   = (const float*)d_in[10];
    const float* p2w  = (const float*)d_in[13];
    const float* p2b  = (const float*)d_in[14];
    const float* ln_g = (const float*)d_in[15];
    const float* ln_b = (const float*)d_in[16];
    const float* fw1  = (const float*)d_in[17];
    const float* fb1  = (const float*)d_in[18];
    const float* fw2  = (const float*)d_in[19];
    const float* fb2  = (const float*)d_in[20];
    const float* fw3  = (const float*)d_in[21];
    const float* fb3  = (const float*)d_in[22];
    const float* fw4  = (const float*)d_in[23];
    const float* fb4  = (const float*)d_in[24];
    const float* lw   = (const float*)d_in[25];
    const float* lb   = (const float*)d_in[26];
    float* out = (float*)d_out;

    float *pH, *pO, *px2, *pe1, *pe2, *pe3, *pe4;
    __nv_bfloat16 *pAhi, *pAlo, *pBhi, *pBlo;
    cudaGetSymbolAddress((void**)&pH,   g_H);
    cudaGetSymbolAddress((void**)&pO,   g_O);
    cudaGetSymbolAddress((void**)&pAhi, g_Ahi);
    cudaGetSymbolAddress((void**)&pAlo, g_Alo);
    cudaGetSymbolAddress((void**)&pBhi, g_Bhi);
    cudaGetSymbolAddress((void**)&pBlo, g_Blo);
    cudaGetSymbolAddress((void**)&px2,  g_x2);
    cudaGetSymbolAddress((void**)&pe1,  g_e1);
    cudaGetSymbolAddress((void**)&pe2,  g_e2);
    cudaGetSymbolAddress((void**)&pe3,  g_e3);
    cudaGetSymbolAddress((void**)&pe4,  g_e4);

    cudaFuncSetAttribute(gemm_bf16split, cudaFuncAttributeMaxDynamicSharedMemorySize, 65536);

    const int eblocks = (ETOT + 255) / 256;
    const int ablocks = (ETOT * 32 + 255) / 256;
    const dim3 gemm_grid(HC / 128, NN / 128);

    // ===== edge-index dtype detect + unpack =====
    detect_kernel<<<1, 256>>>(eibuf);
    convert_kernel<<<eblocks, 256>>>(eibuf);

    // ===== GAT layer 1 =====
    split_kernel<<<(NN * DIN / 4) / 256, 256>>>(x, pAhi, pAlo);
    split_kernel<<<(DIN * HC / 4) / 256, 256>>>(W1, pBhi, pBlo);
    gemm_bf16split<<<gemm_grid, 256, 65536>>>(pAhi, pAlo, pBhi, pBlo, pH, NN, HC, DIN);
    alphas_kernel<<<NN, 128>>>(as1, ad1);
    init_layer<<<(NN * HC / 4) / 256, 256>>>();
    edge_max<<<eblocks, 256>>>();
    edge_expsum<<<eblocks, 256>>>();
    edge_aggregate<<<ablocks, 256>>>();
    bias_elu<<<(NN * HC) / 256, 256>>>(b1);          // g_O = h1

    // ===== GAT layer 2 =====
    split_kernel<<<(NN * HC / 4) / 256, 256>>>(pO, pAhi, pAlo);
    split_kernel<<<(HC * HC / 4) / 256, 256>>>(W2, pBhi, pBlo);
    gemm_bf16split<<<gemm_grid, 256, 65536>>>(pAhi, pAlo, pBhi, pBlo, pH, NN, HC, HC);
    alphas_kernel<<<NN, 128>>>(as2, ad2);
    init_layer<<<(NN * HC / 4) / 256, 256>>>();
    edge_max<<<eblocks, 256>>>();
    edge_expsum<<<eblocks, 256>>>();
    edge_aggregate<<<ablocks, 256>>>();
    bias_elu<<<(NN * HC) / 256, 256>>>(b2);          // g_O = h2

    // ===== pooling + layer norm =====
    pool2_kernel<<<(NN * 32) / 256, 256>>>(p2w, p2b);
    ln_kernel<<<BB, 256>>>(ln_g, ln_b, out);

    // ===== encoder MLP =====
    fc_kernel<<<dim3(4, BB), 128>>>(px2, fw1, fb1, pe1, 1024, 512, 1);
    fc_kernel<<<dim3(2, BB), 128>>>(pe1, fw2, fb2, pe2, 512, 256, 1);
    fc_kernel<<<dim3(1, BB), 128>>>(pe2, fw3, fb3, pe3, 256, 128, 1);
    fc_kernel<<<dim3(1, BB), 128>>>(pe3, fw4, fb4, pe4, 128, 64, 1);
    final_kernel<<<BB, 64>>>(lw, lb, out);
}

// round 6
// speedup vs baseline: 1.7018x; 1.2116x over previous
#include <cuda_runtime.h>
#include <cuda_bf16.h>
#include <cstdint>
#include <cstddef>

// ---------------- problem constants ----------------
#define NN     16384
#define DIN    1024
#define HH     4
#define CC     128
#define HC     512
#define EE     262144
#define ETOT   (EE + NN)
#define BB     16
#define NODES  1024

// ---------------- device scratch ----------------
__device__ float         g_H[(size_t)NN * HC];
__device__ float         g_O[(size_t)NN * HC];
__device__ __nv_bfloat16 g_Ahi[(size_t)NN * DIN];
__device__ __nv_bfloat16 g_Alo[(size_t)NN * DIN];
__device__ __nv_bfloat16 g_Bhi[DIN * HC];
__device__ __nv_bfloat16 g_Blo[DIN * HC];
__device__ float         g_as[NN * HH];
__device__ float         g_ad[NN * HH];
__device__ float         g_invden[NN * HH];
__device__ float         g_ew[(size_t)ETOT * HH];
__device__ int           g_src[ETOT];
__device__ int           g_dst[ETOT];
__device__ int           g_deg[NN];
__device__ int           g_cur[NN];
__device__ int           g_off[NN + 1];
__device__ int           g_eid[ETOT];
__device__ int           g_is64;
__device__ float         g_x2[BB * NODES];
__device__ float         g_e1[BB * 512];
__device__ float         g_e2[BB * 256];
__device__ float         g_e3[BB * 128];
__device__ float         g_e4[BB * 64];

// ---------------- helpers ----------------
__device__ __forceinline__ float wsum(float v) {
#pragma unroll
    for (int o = 16; o > 0; o >>= 1) v += __shfl_xor_sync(0xffffffffu, v, o);
    return v;
}
__device__ __forceinline__ float wmax(float v) {
#pragma unroll
    for (int o = 16; o > 0; o >>= 1) v = fmaxf(v, __shfl_xor_sync(0xffffffffu, v, o));
    return v;
}
__device__ __forceinline__ float lrelu(float x) { return (x > 0.f) ? x : 0.2f * x; }
__device__ __forceinline__ void cp16(unsigned s, const void* g) {
    asm volatile("cp.async.cg.shared.global [%0], [%1], 16;" :: "r"(s), "l"(g));
}
__device__ __forceinline__ void ldsm4(unsigned* r, unsigned a) {
    asm volatile("ldmatrix.sync.aligned.m8n8.x4.shared.b16 {%0,%1,%2,%3}, [%4];"
                 : "=r"(r[0]), "=r"(r[1]), "=r"(r[2]), "=r"(r[3]) : "r"(a));
}
__device__ __forceinline__ void ldsm4t(unsigned* r, unsigned a) {
    asm volatile("ldmatrix.sync.aligned.m8n8.x4.trans.shared.b16 {%0,%1,%2,%3}, [%4];"
                 : "=r"(r[0]), "=r"(r[1]), "=r"(r[2]), "=r"(r[3]) : "r"(a));
}
__device__ __forceinline__ void mma16816(float* c, const unsigned* a, const unsigned* b) {
    asm volatile("mma.sync.aligned.m16n8k16.row.col.f32.bf16.bf16.f32 "
                 "{%0,%1,%2,%3}, {%4,%5,%6,%7}, {%8,%9}, {%0,%1,%2,%3};"
                 : "+f"(c[0]), "+f"(c[1]), "+f"(c[2]), "+f"(c[3])
                 : "r"(a[0]), "r"(a[1]), "r"(a[2]), "r"(a[3]), "r"(b[0]), "r"(b[1]));
}

// ---------------- fp32 -> bf16 hi/lo split ----------------
__global__ void split_kernel(const float* __restrict__ x, __nv_bfloat16* __restrict__ hi,
                             __nv_bfloat16* __restrict__ lo) {
    const size_t i = (size_t)blockIdx.x * blockDim.x + threadIdx.x;
    const float4 v = ((const float4*)x)[i];
    const __nv_bfloat16 h0 = __float2bfloat16(v.x), h1 = __float2bfloat16(v.y);
    const __nv_bfloat16 h2 = __float2bfloat16(v.z), h3 = __float2bfloat16(v.w);
    const __nv_bfloat16 l0 = __float2bfloat16(v.x - __bfloat162float(h0));
    const __nv_bfloat16 l1 = __float2bfloat16(v.y - __bfloat162float(h1));
    const __nv_bfloat16 l2 = __float2bfloat16(v.z - __bfloat162float(h2));
    const __nv_bfloat16 l3 = __float2bfloat16(v.w - __bfloat162float(h3));
    __nv_bfloat162* hp = (__nv_bfloat162*)hi;
    __nv_bfloat162* lp = (__nv_bfloat162*)lo;
    hp[2 * i]     = __halves2bfloat162(h0, h1);
    hp[2 * i + 1] = __halves2bfloat162(h2, h3);
    lp[2 * i]     = __halves2bfloat162(l0, l1);
    lp[2 * i + 1] = __halves2bfloat162(l2, l3);
}

// ---------------- bf16-split tensor GEMM (128x128x32, 8 warps, double-buffered) ----------------
__global__ __launch_bounds__(256)
void gemm_bf16split(const __nv_bfloat16* __restrict__ Ahi, const __nv_bfloat16* __restrict__ Alo,
                    const __nv_bfloat16* __restrict__ Bhi, const __nv_bfloat16* __restrict__ Blo,
                    float* __restrict__ C, int M, int N, int K) {
    extern __shared__ __nv_bfloat16 sm[];
    const int tid   = threadIdx.x;
    const int mBase = blockIdx.y * 128;
    const int nBase = blockIdx.x * 128;
    const unsigned sbase = (unsigned)__cvta_generic_to_shared(sm);

    const int wid = tid >> 5, lane = tid & 31;
    const int wm = wid & 3;
    const int wn = wid >> 2;

    float acc[2][8][4];
#pragma unroll
    for (int i = 0; i < 2; i++)
#pragma unroll
        for (int j = 0; j < 8; j++)
#pragma unroll
            for (int k = 0; k < 4; k++) acc[i][j][k] = 0.f;

    auto load_stage = [&](int stage, int kt) {
        const int kb = kt * 32;
#pragma unroll
        for (int i = 0; i < 2; i++) {
            const int chunk = tid + (i << 8);
            const int row = chunk >> 2, u = chunk & 3;
            const int su = u ^ ((row >> 1) & 3);
            const size_t goff = (size_t)(mBase + row) * K + kb + u * 8;
            const unsigned s0 = sbase + (unsigned)((stage * 2) * 4096 + row * 32 + su * 8) * 2;
            cp16(s0,            Ahi + goff);
            cp16(s0 + 4096 * 2, Alo + goff);
        }
#pragma unroll
        for (int i = 0; i < 2; i++) {
            const int chunk = tid + (i << 8);
            const int row = chunk >> 4, u = chunk & 15;
            const int su = u ^ (row & 7);
            const size_t goff = (size_t)(kb + row) * N + nBase + u * 8;
            const unsigned s0 = sbase + (unsigned)(16384 + (stage * 2) * 4096 + row * 128 + su * 8) * 2;
            cp16(s0,            Bhi + goff);
            cp16(s0 + 4096 * 2, Blo + goff);
        }
    };

    const int nk = K >> 5;
    load_stage(0, 0);
    asm volatile("cp.async.commit_group;");

    for (int kt = 0; kt < nk; kt++) {
        if (kt + 1 < nk) load_stage((kt + 1) & 1, kt + 1);
        asm volatile("cp.async.commit_group;");
        asm volatile("cp.async.wait_group 1;");
        __syncthreads();

        const int stage = kt & 1;
        const unsigned aStage = sbase + (unsigned)((stage * 2) * 4096) * 2;
        const unsigned bStage = sbase + (unsigned)(16384 + (stage * 2) * 4096) * 2;
#pragma unroll
        for (int kk = 0; kk < 2; kk++) {
            unsigned ah[2][4], al[2][4], bh[4][4], bl[4][4];
#pragma unroll
            for (int mt = 0; mt < 2; mt++) {
                const int row = wm * 32 + mt * 16 + (lane & 15);
                const int u = (kk * 2 + (lane >> 4)) ^ ((row >> 1) & 3);
                const unsigned ad = aStage + (unsigned)(row * 32 + u * 8) * 2;
                ldsm4(ah[mt], ad);
                ldsm4(al[mt], ad + 4096 * 2);
            }
#pragma unroll
            for (int nt = 0; nt < 4; nt++) {
                const int row = kk * 16 + (lane & 15);
                const int u = (wn * 8 + nt * 2 + (lane >> 4)) ^ (row & 7);
                const unsigned bd = bStage + (unsigned)(row * 128 + u * 8) * 2;
                ldsm4t(bh[nt], bd);
                ldsm4t(bl[nt], bd + 4096 * 2);
            }
#pragma unroll
            for (int mt = 0; mt < 2; mt++)
#pragma unroll
                for (int n8 = 0; n8 < 8; n8++)
                    mma16816(acc[mt][n8], ah[mt], &bh[n8 >> 1][(n8 & 1) * 2]);
#pragma unroll
            for (int mt = 0; mt < 2; mt++)
#pragma unroll
                for (int n8 = 0; n8 < 8; n8++)
                    mma16816(acc[mt][n8], ah[mt], &bl[n8 >> 1][(n8 & 1) * 2]);
#pragma unroll
            for (int mt = 0; mt < 2; mt++)
#pragma unroll
                for (int n8 = 0; n8 < 8; n8++)
                    mma16816(acc[mt][n8], al[mt], &bh[n8 >> 1][(n8 & 1) * 2]);
        }
        __syncthreads();
    }

#pragma unroll
    for (int mt = 0; mt < 2; mt++) {
#pragma unroll
        for (int n8 = 0; n8 < 8; n8++) {
            const int row0 = mBase + wm * 32 + mt * 16 + (lane >> 2);
            const int col  = nBase + wn * 64 + n8 * 8 + (lane & 3) * 2;
            *(float2*)&C[(size_t)row0 * N + col]       = make_float2(acc[mt][n8][0], acc[mt][n8][1]);
            *(float2*)&C[(size_t)(row0 + 8) * N + col] = make_float2(acc[mt][n8][2], acc[mt][n8][3]);
        }
    }
}

// ---------------- edge index dtype detection ----------------
__global__ void detect_kernel(const int* __restrict__ buf) {
    __shared__ int sh[256];
    int v = 0;
    for (int i = threadIdx.x; i < 8192; i += 256) v |= buf[2 * i + 1];
    sh[threadIdx.x] = v;
    __syncthreads();
    for (int s = 128; s > 0; s >>= 1) {
        if (threadIdx.x < s) sh[threadIdx.x] |= sh[threadIdx.x + s];
        __syncthreads();
    }
    if (threadIdx.x == 0) g_is64 = (sh[0] == 0) ? 1 : 0;
}

__global__ void zero_counts() {
    const int i = blockIdx.x * blockDim.x + threadIdx.x;
    if (i < NN) { g_deg[i] = 0; g_cur[i] = 0; }
}

// convert + degree count
__global__ void convert_kernel(const int* __restrict__ buf) {
    const int e = blockIdx.x * blockDim.x + threadIdx.x;
    if (e >= ETOT) return;
    int s, d;
    if (e >= EE) { s = d = e - EE; }
    else if (g_is64) { s = buf[2 * e]; d = buf[2 * (EE + e)]; }
    else             { s = buf[e];     d = buf[EE + e]; }
    g_src[e] = s; g_dst[e] = d;
    atomicAdd(&g_deg[d], 1);
}

// exclusive scan of g_deg -> g_off (single block, 1024 threads)
__global__ void scan_kernel() {
    __shared__ int wsums[32];
    __shared__ int s_carry, s_total;
    const int tid = threadIdx.x, lane = tid & 31, wid = tid >> 5;
    if (tid == 0) s_carry = 0;
    __syncthreads();
    for (int c = 0; c < NN; c += 1024) {
        const int i = c + tid;
        const int v = g_deg[i];
        int x = v;
#pragma unroll
        for (int o = 1; o < 32; o <<= 1) {
            const int y = __shfl_up_sync(0xffffffffu, x, o);
            if (lane >= o) x += y;
        }
        if (lane == 31) wsums[wid] = x;
        __syncthreads();
        if (tid < 32) {
            const int t = wsums[tid];
            int tx = t;
#pragma unroll
            for (int o = 1; o < 32; o <<= 1) {
                const int y = __shfl_up_sync(0xffffffffu, tx, o);
                if (tid >= o) tx += y;
            }
            wsums[tid] = tx - t;
            if (tid == 31) s_total = tx;
        }
        __syncthreads();
        g_off[i] = s_carry + wsums[wid] + (x - v);
        __syncthreads();
        if (tid == 0) s_carry += s_total;
        __syncthreads();
    }
    if (tid == 0) g_off[NN] = s_carry;
}

__global__ void scatter_kernel() {
    const int e = blockIdx.x * blockDim.x + threadIdx.x;
    if (e >= ETOT) return;
    const int d = g_dst[e];
    const int pos = atomicAdd(&g_cur[d], 1);
    g_eid[g_off[d] + pos] = e;
}

// ---------------- attention coefficients ----------------
__global__ void alphas_kernel(const float* __restrict__ asrc, const float* __restrict__ adst) {
    const int n = blockIdx.x;
    const int h = threadIdx.x >> 5, lane = threadIdx.x & 31;
    const float4 hv = *(const float4*)&g_H[(size_t)n * HC + h * CC + lane * 4];
    const float4 s4 = *(const float4*)&asrc[h * CC + lane * 4];
    const float4 d4 = *(const float4*)&adst[h * CC + lane * 4];
    float ss = hv.x * s4.x + hv.y * s4.y + hv.z * s4.z + hv.w * s4.w;
    float sd = hv.x * d4.x + hv.y * d4.y + hv.z * d4.z + hv.w * d4.w;
    ss = wsum(ss); sd = wsum(sd);
    if (lane == 0) { g_as[n * HH + h] = ss; g_ad[n * HH + h] = sd; }
}

// ---------------- CSR softmax: warp per node, no atomics ----------------
__global__ __launch_bounds__(128)
void csr_softmax() {
    const int warp = threadIdx.x >> 5, lane = threadIdx.x & 31;
    const int n = blockIdx.x * 4 + warp;
    const int off0 = g_off[n];
    const int deg  = g_off[n + 1] - off0;
    const float4 adp = *(const float4*)&g_ad[n * HH];
    float m0 = -1e30f, m1 = -1e30f, m2 = -1e30f, m3 = -1e30f;
    for (int j = lane; j < deg; j += 32) {
        const int eid = g_eid[off0 + j];
        const float4 a = *(const float4*)&g_as[g_src[eid] * HH];
        m0 = fmaxf(m0, lrelu(a.x + adp.x));
        m1 = fmaxf(m1, lrelu(a.y + adp.y));
        m2 = fmaxf(m2, lrelu(a.z + adp.z));
        m3 = fmaxf(m3, lrelu(a.w + adp.w));
    }
    m0 = wmax(m0); m1 = wmax(m1); m2 = wmax(m2); m3 = wmax(m3);
    float s0 = 0.f, s1 = 0.f, s2 = 0.f, s3 = 0.f;
    for (int j = lane; j < deg; j += 32) {
        const int eid = g_eid[off0 + j];
        const float4 a = *(const float4*)&g_as[g_src[eid] * HH];
        const float e0 = __expf(lrelu(a.x + adp.x) - m0);
        const float e1 = __expf(lrelu(a.y + adp.y) - m1);
        const float e2 = __expf(lrelu(a.z + adp.z) - m2);
        const float e3 = __expf(lrelu(a.w + adp.w) - m3);
        s0 += e0; s1 += e1; s2 += e2; s3 += e3;
        *(float4*)&g_ew[(size_t)eid * HH] = make_float4(e0, e1, e2, e3);
    }
    s0 = wsum(s0); s1 = wsum(s1); s2 = wsum(s2); s3 = wsum(s3);
    if (lane == 0)
        *(float4*)&g_invden[n * HH] = make_float4(1.f / (s0 + 1e-16f), 1.f / (s1 + 1e-16f),
                                                  1.f / (s2 + 1e-16f), 1.f / (s3 + 1e-16f));
}

// ---------------- CSR aggregate: warp per (node, head); gather + register accumulate ----------------
// mode 0: out = elu(acc + bias) -> g_O      (layer 1)
// mode 1: dot(elu(acc + bias), p2w) -> red.add g_x2[n]   (layer 2, h2 never materialized)
__global__ __launch_bounds__(256)
void csr_aggregate(const float* __restrict__ bias, const float* __restrict__ pw, int mode) {
    const int w = blockIdx.x * 8 + (threadIdx.x >> 5);
    const int lane = threadIdx.x & 31;
    const int n = w >> 2, h = w & 3;
    const int off0 = g_off[n];
    const int deg  = g_off[n + 1] - off0;
    const float invd = g_invden[n * HH + h];
    float4 acc = make_float4(0.f, 0.f, 0.f, 0.f);
    for (int base = 0; base < deg; base += 32) {
        const int cnt = min(32, deg - base);
        int s = 0; float wgt = 0.f;
        if (lane < cnt) {
            const int eid = g_eid[off0 + base + lane];
            s   = g_src[eid];
            wgt = g_ew[(size_t)eid * HH + h];
        }
        for (int j = 0; j < cnt; j++) {
            const int   ss = __shfl_sync(0xffffffffu, s, j);
            const float ww = __shfl_sync(0xffffffffu, wgt, j) * invd;
            const float4 v = *(const float4*)&g_H[(size_t)ss * HC + h * CC + lane * 4];
            acc.x += v.x * ww; acc.y += v.y * ww; acc.z += v.z * ww; acc.w += v.w * ww;
        }
    }
    const float4 b4 = *(const float4*)&bias[h * CC + lane * 4];
    float4 v = make_float4(acc.x + b4.x, acc.y + b4.y, acc.z + b4.z, acc.w + b4.w);
    v.x = (v.x > 0.f) ? v.x : expm1f(v.x);
    v.y = (v.y > 0.f) ? v.y : expm1f(v.y);
    v.z = (v.z > 0.f) ? v.z : expm1f(v.z);
    v.w = (v.w > 0.f) ? v.w : expm1f(v.w);
    if (mode == 0) {
        *(float4*)&g_O[(size_t)n * HC + h * CC + lane * 4] = v;
    } else {
        const float4 p = *(const float4*)&pw[h * CC + lane * 4];
        float dot = v.x * p.x + v.y * p.y + v.z * p.z + v.w * p.w;
        dot = wsum(dot);
        if (lane == 0)
            asm volatile("red.global.add.f32 [%0], %1;" :: "l"(&g_x2[n]), "f"(dot) : "memory");
    }
}

// ---------------- x2 init (= p2b) ----------------
__global__ void x2_init(const float* __restrict__ p2b) {
    const int i = blockIdx.x * blockDim.x + threadIdx.x;
    if (i < BB * NODES) g_x2[i] = p2b[0];
}

// ---------------- layer norm ----------------
__global__ void ln_kernel(const float* __restrict__ g, const float* __restrict__ be,
                          float* __restrict__ out) {
    const int bb = blockIdx.x, tid = threadIdx.x;
    const int lane = tid & 31, wid = tid >> 5;
    float s = 0.f, s2 = 0.f;
    for (int i = tid; i < NODES; i += 256) {
        const float v = g_x2[bb * NODES + i];
        s += v; s2 += v * v;
    }
    s = wsum(s); s2 = wsum(s2);
    __shared__ float shs[8], shs2[8];
    if (lane == 0) { shs[wid] = s; shs2[wid] = s2; }
    __syncthreads();
    __shared__ float smu, srv;
    if (tid == 0) {
        float S = 0.f, S2 = 0.f;
        for (int w = 0; w < 8; w++) { S += shs[w]; S2 += shs2[w]; }
        const float mu = S / NODES;
        smu = mu;
        srv = rsqrtf(S2 / NODES - mu * mu + 1e-5f);
    }
    __syncthreads();
    const float mu = smu, rv = srv;
    for (int i = tid; i < NODES; i += 256) {
        const float v = (g_x2[bb * NODES + i] - mu) * rv * g[i] + be[i];
        out[bb * NODES + i] = v;
        g_x2[bb * NODES + i] = v;
    }
}

// ---------------- small FC ----------------
__global__ void fc_kernel(const float* __restrict__ in, const float* __restrict__ W,
                          const float* __restrict__ bias, float* __restrict__ out,
                          int Din, int Dout, int act) {
    const int j = blockIdx.x * blockDim.x + threadIdx.x;
    const int b = blockIdx.y;
    if (j >= Dout) return;
    const float* ir = in + (size_t)b * Din;
    float s = bias[j];
    for (int k = 0; k < Din; k++) s += ir[k] * W[(size_t)k * Dout + j];
    if (act) s = (s > 0.f) ? s : expm1f(s);
    out[b * Dout + j] = s;
}

// ---------------- final ----------------
__global__ void final_kernel(const float* __restrict__ lw, const float* __restrict__ lb,
                             float* __restrict__ out) {
    const int b = blockIdx.x, tid = threadIdx.x;
    const float v = g_e4[b * 64 + tid];
    out[BB * NODES + b * 64 + tid] = v;
    float p = v * lw[tid];
#pragma unroll
    for (int o = 16; o > 0; o >>= 1) p += __shfl_xor_sync(0xffffffffu, p, o);
    __shared__ float sh[2];
    if ((tid & 31) == 0) sh[tid >> 5] = p;
    __syncthreads();
    if (tid == 0) out[BB * NODES + BB * 64 + b] = sh[0] + sh[1] + lb[0];
}

// ---------------- launch ----------------
extern "C" void kernel_launch(void* const* d_in, const int* in_sizes, int n_in,
                              void* d_out, int out_size) {
    const float* x     = (const float*)d_in[0];
    const int*   eibuf = (const int*)d_in[1];
    const float* W1   = (const float*)d_in[3];
    const float* as1  = (const float*)d_in[4];
    const float* ad1  = (const float*)d_in[5];
    const float* b1   = (const float*)d_in[6];
    const float* W2   = (const float*)d_in[7];
    const float* as2  = (const float*)d_in[8];
    const float* ad2  = (const float*)d_in[9];
    const float* b2   = (const float*)d_in[10];
    const float* p2w  = (const float*)d_in[13];
    const float* p2b  = (const float*)d_in[14];
    const float* ln_g = (const float*)d_in[15];
    const float* ln_b = (const float*)d_in[16];
    const float* fw1  = (const float*)d_in[17];
    const float* fb1  = (const float*)d_in[18];
    const float* fw2  = (const float*)d_in[19];
    const float* fb2  = (const float*)d_in[20];
    const float* fw3  = (const float*)d_in[21];
    const float* fb3  = (const float*)d_in[22];
    const float* fw4  = (const float*)d_in[23];
    const float* fb4  = (const float*)d_in[24];
    const float* lw   = (const float*)d_in[25];
    const float* lb   = (const float*)d_in[26];
    float* out = (float*)d_out;

    float *pH, *pO, *px2, *pe1, *pe2, *pe3, *pe4;
    __nv_bfloat16 *pAhi, *pAlo, *pBhi, *pBlo;
    cudaGetSymbolAddress((void**)&pH,   g_H);
    cudaGetSymbolAddress((void**)&pO,   g_O);
    cudaGetSymbolAddress((void**)&pAhi, g_Ahi);
    cudaGetSymbolAddress((void**)&pAlo, g_Alo);
    cudaGetSymbolAddress((void**)&pBhi, g_Bhi);
    cudaGetSymbolAddress((void**)&pBlo, g_Blo);
    cudaGetSymbolAddress((void**)&px2,  g_x2);
    cudaGetSymbolAddress((void**)&pe1,  g_e1);
    cudaGetSymbolAddress((void**)&pe2,  g_e2);
    cudaGetSymbolAddress((void**)&pe3,  g_e3);
    cudaGetSymbolAddress((void**)&pe4,  g_e4);

    cudaFuncSetAttribute(gemm_bf16split, cudaFuncAttributeMaxDynamicSharedMemorySize, 65536);

    const int eblocks = (ETOT + 255) / 256;
    const dim3 gemm_grid(HC / 128, NN / 128);

    // ===== CSR build (edges shared by both layers) =====
    detect_kernel<<<1, 256>>>(eibuf);
    zero_counts<<<NN / 256, 256>>>();
    convert_kernel<<<eblocks, 256>>>(eibuf);
    scan_kernel<<<1, 1024>>>();
    scatter_kernel<<<eblocks, 256>>>();

    // ===== GAT layer 1 =====
    split_kernel<<<(NN * DIN / 4) / 256, 256>>>(x, pAhi, pAlo);
    split_kernel<<<(DIN * HC / 4) / 256, 256>>>(W1, pBhi, pBlo);
    gemm_bf16split<<<gemm_grid, 256, 65536>>>(pAhi, pAlo, pBhi, pBlo, pH, NN, HC, DIN);
    alphas_kernel<<<NN, 128>>>(as1, ad1);
    csr_softmax<<<NN / 4, 128>>>();
    csr_aggregate<<<NN * HH / 8, 256>>>(b1, nullptr, 0);   // g_O = h1

    // ===== GAT layer 2 =====
    split_kernel<<<(NN * HC / 4) / 256, 256>>>(pO, pAhi, pAlo);
    split_kernel<<<(HC * HC / 4) / 256, 256>>>(W2, pBhi, pBlo);
    gemm_bf16split<<<gemm_grid, 256, 65536>>>(pAhi, pAlo, pBhi, pBlo, pH, NN, HC, HC);
    alphas_kernel<<<NN, 128>>>(as2, ad2);
    csr_softmax<<<NN / 4, 128>>>();
    x2_init<<<(BB * NODES) / 256, 256>>>(p2b);
    csr_aggregate<<<NN * HH / 8, 256>>>(b2, p2w, 1);       // x2 via fused pool, h2 never stored

    // ===== layer norm -> d_out[0:16384) =====
    ln_kernel<<<BB, 256>>>(ln_g, ln_b, out);

    // ===== encoder MLP =====
    fc_kernel<<<dim3(4, BB), 128>>>(px2, fw1, fb1, pe1, 1024, 512, 1);
    fc_kernel<<<dim3(2, BB), 128>>>(pe1, fw2, fb2, pe2, 512, 256, 1);
    fc_kernel<<<dim3(1, BB), 128>>>(pe2, fw3, fb3, pe3, 256, 128, 1);
    fc_kernel<<<dim3(1, BB), 128>>>(pe3, fw4, fb4, pe4, 128, 64, 1);
    final_kernel<<<BB, 64>>>(lw, lb, out);
}

// round 7
// speedup vs baseline: 1.8501x; 1.0872x over previous
#include <cuda_runtime.h>
#include <cuda_bf16.h>
#include <cstdint>
#include <cstddef>

// ---------------- problem constants ----------------
#define NN     16384
#define DIN    1024
#define HH     4
#define CC     128
#define HC     512
#define EE     262144
#define ETOT   (EE + NN)
#define BB     16
#define NODES  1024
#define NBLK   64          // scan blocks (NN/256)

// ---------------- device scratch ----------------
__device__ float         g_H[(size_t)NN * HC];
__device__ __nv_bfloat16 g_Ahi[(size_t)NN * DIN];
__device__ __nv_bfloat16 g_Alo[(size_t)NN * DIN];
__device__ __nv_bfloat16 g_Bhi[DIN * HC];
__device__ __nv_bfloat16 g_Blo[DIN * HC];
__device__ float         g_as[NN * HH];
__device__ float         g_ad[NN * HH];
__device__ float         g_invden[NN * HH];
__device__ float         g_mx[NN * HH];
__device__ float         g_xw[(size_t)ETOT * HH];   // per-slot logits (CSR order)
__device__ int           g_src[ETOT];
__device__ int           g_dst[ETOT];
__device__ int           g_csrc[ETOT];              // CSR-ordered sources
__device__ int           g_deg[NN];
__device__ int           g_cur[NN];
__device__ int           g_off[NN + 1];
__device__ int           g_bsum[NBLK];
__device__ int           g_is64;
__device__ float         g_x2[BB * NODES];
__device__ float         g_e1[BB * 512];
__device__ float         g_e2[BB * 256];
__device__ float         g_e3[BB * 128];
__device__ float         g_e4[BB * 64];

// ---------------- helpers ----------------
__device__ __forceinline__ float wsum(float v) {
#pragma unroll
    for (int o = 16; o > 0; o >>= 1) v += __shfl_xor_sync(0xffffffffu, v, o);
    return v;
}
__device__ __forceinline__ float wmax(float v) {
#pragma unroll
    for (int o = 16; o > 0; o >>= 1) v = fmaxf(v, __shfl_xor_sync(0xffffffffu, v, o));
    return v;
}
__device__ __forceinline__ float lrelu(float x) { return (x > 0.f) ? x : 0.2f * x; }
__device__ __forceinline__ void cp16(unsigned s, const void* g) {
    asm volatile("cp.async.cg.shared.global [%0], [%1], 16;" :: "r"(s), "l"(g));
}
__device__ __forceinline__ void ldsm4(unsigned* r, unsigned a) {
    asm volatile("ldmatrix.sync.aligned.m8n8.x4.shared.b16 {%0,%1,%2,%3}, [%4];"
                 : "=r"(r[0]), "=r"(r[1]), "=r"(r[2]), "=r"(r[3]) : "r"(a));
}
__device__ __forceinline__ void ldsm4t(unsigned* r, unsigned a) {
    asm volatile("ldmatrix.sync.aligned.m8n8.x4.trans.shared.b16 {%0,%1,%2,%3}, [%4];"
                 : "=r"(r[0]), "=r"(r[1]), "=r"(r[2]), "=r"(r[3]) : "r"(a));
}
__device__ __forceinline__ void mma16816(float* c, const unsigned* a, const unsigned* b) {
    asm volatile("mma.sync.aligned.m16n8k16.row.col.f32.bf16.bf16.f32 "
                 "{%0,%1,%2,%3}, {%4,%5,%6,%7}, {%8,%9}, {%0,%1,%2,%3};"
                 : "+f"(c[0]), "+f"(c[1]), "+f"(c[2]), "+f"(c[3])
                 : "r"(a[0]), "r"(a[1]), "r"(a[2]), "r"(a[3]), "r"(b[0]), "r"(b[1]));
}
__device__ __forceinline__ unsigned pack_bf2(float a, float b) {
    __nv_bfloat162 t = __halves2bfloat162(__float2bfloat16(a), __float2bfloat16(b));
    return *(unsigned*)&t;
}

// ---------------- fp32 -> bf16 hi/lo split ----------------
__global__ void split_kernel(const float* __restrict__ x, __nv_bfloat16* __restrict__ hi,
                             __nv_bfloat16* __restrict__ lo) {
    const size_t i = (size_t)blockIdx.x * blockDim.x + threadIdx.x;
    const float4 v = ((const float4*)x)[i];
    const float h0 = __bfloat162float(__float2bfloat16(v.x));
    const float h1 = __bfloat162float(__float2bfloat16(v.y));
    const float h2 = __bfloat162float(__float2bfloat16(v.z));
    const float h3 = __bfloat162float(__float2bfloat16(v.w));
    ((uint2*)hi)[i] = make_uint2(pack_bf2(v.x, v.y), pack_bf2(v.z, v.w));
    ((uint2*)lo)[i] = make_uint2(pack_bf2(v.x - h0, v.y - h1), pack_bf2(v.z - h2, v.w - h3));
}

// ---------------- bf16-split tensor GEMM + fused alpha dots ----------------
// N-tile 128 == one head: block (bx=head, by=mtile) also computes
// g_as/g_ad[row, head] = <C_row, att_src/att_dst[head]>.
__global__ __launch_bounds__(256)
void gemm_bf16split(const __nv_bfloat16* __restrict__ Ahi, const __nv_bfloat16* __restrict__ Alo,
                    const __nv_bfloat16* __restrict__ Bhi, const __nv_bfloat16* __restrict__ Blo,
                    float* __restrict__ C, int M, int N, int K,
                    const float* __restrict__ attS, const float* __restrict__ attD) {
    extern __shared__ __nv_bfloat16 sm[];
    __shared__ float s_att[2][128];
    __shared__ float sredS[2][128], sredD[2][128];
    const int tid   = threadIdx.x;
    const int mBase = blockIdx.y * 128;
    const int nBase = blockIdx.x * 128;
    const unsigned sbase = (unsigned)__cvta_generic_to_shared(sm);

    if (tid < 128) {
        s_att[0][tid] = attS[nBase + tid];
        s_att[1][tid] = attD[nBase + tid];
    }

    const int wid = tid >> 5, lane = tid & 31;
    const int wm = wid & 3;
    const int wn = wid >> 2;

    float acc[2][8][4];
#pragma unroll
    for (int i = 0; i < 2; i++)
#pragma unroll
        for (int j = 0; j < 8; j++)
#pragma unroll
            for (int k = 0; k < 4; k++) acc[i][j][k] = 0.f;

    auto load_stage = [&](int stage, int kt) {
        const int kb = kt * 32;
#pragma unroll
        for (int i = 0; i < 2; i++) {
            const int chunk = tid + (i << 8);
            const int row = chunk >> 2, u = chunk & 3;
            const int su = u ^ ((row >> 1) & 3);
            const size_t goff = (size_t)(mBase + row) * K + kb + u * 8;
            const unsigned s0 = sbase + (unsigned)((stage * 2) * 4096 + row * 32 + su * 8) * 2;
            cp16(s0,            Ahi + goff);
            cp16(s0 + 4096 * 2, Alo + goff);
        }
#pragma unroll
        for (int i = 0; i < 2; i++) {
            const int chunk = tid + (i << 8);
            const int row = chunk >> 4, u = chunk & 15;
            const int su = u ^ (row & 7);
            const size_t goff = (size_t)(kb + row) * N + nBase + u * 8;
            const unsigned s0 = sbase + (unsigned)(16384 + (stage * 2) * 4096 + row * 128 + su * 8) * 2;
            cp16(s0,            Bhi + goff);
            cp16(s0 + 4096 * 2, Blo + goff);
        }
    };

    const int nk = K >> 5;
    load_stage(0, 0);
    asm volatile("cp.async.commit_group;");

    for (int kt = 0; kt < nk; kt++) {
        if (kt + 1 < nk) load_stage((kt + 1) & 1, kt + 1);
        asm volatile("cp.async.commit_group;");
        asm volatile("cp.async.wait_group 1;");
        __syncthreads();

        const int stage = kt & 1;
        const unsigned aStage = sbase + (unsigned)((stage * 2) * 4096) * 2;
        const unsigned bStage = sbase + (unsigned)(16384 + (stage * 2) * 4096) * 2;
#pragma unroll
        for (int kk = 0; kk < 2; kk++) {
            unsigned ah[2][4], al[2][4], bh[4][4], bl[4][4];
#pragma unroll
            for (int mt = 0; mt < 2; mt++) {
                const int row = wm * 32 + mt * 16 + (lane & 15);
                const int u = (kk * 2 + (lane >> 4)) ^ ((row >> 1) & 3);
                const unsigned ad = aStage + (unsigned)(row * 32 + u * 8) * 2;
                ldsm4(ah[mt], ad);
                ldsm4(al[mt], ad + 4096 * 2);
            }
#pragma unroll
            for (int nt = 0; nt < 4; nt++) {
                const int row = kk * 16 + (lane & 15);
                const int u = (wn * 8 + nt * 2 + (lane >> 4)) ^ (row & 7);
                const unsigned bd = bStage + (unsigned)(row * 128 + u * 8) * 2;
                ldsm4t(bh[nt], bd);
                ldsm4t(bl[nt], bd + 4096 * 2);
            }
#pragma unroll
            for (int mt = 0; mt < 2; mt++)
#pragma unroll
                for (int n8 = 0; n8 < 8; n8++)
                    mma16816(acc[mt][n8], ah[mt], &bh[n8 >> 1][(n8 & 1) * 2]);
#pragma unroll
            for (int mt = 0; mt < 2; mt++)
#pragma unroll
                for (int n8 = 0; n8 < 8; n8++)
                    mma16816(acc[mt][n8], ah[mt], &bl[n8 >> 1][(n8 & 1) * 2]);
#pragma unroll
            for (int mt = 0; mt < 2; mt++)
#pragma unroll
                for (int n8 = 0; n8 < 8; n8++)
                    mma16816(acc[mt][n8], al[mt], &bh[n8 >> 1][(n8 & 1) * 2]);
        }
        __syncthreads();
    }

    // C store + fused alpha partials
    float psS[4] = {0.f, 0.f, 0.f, 0.f};
    float psD[4] = {0.f, 0.f, 0.f, 0.f};
#pragma unroll
    for (int mt = 0; mt < 2; mt++) {
#pragma unroll
        for (int n8 = 0; n8 < 8; n8++) {
            const int row0 = mBase + wm * 32 + mt * 16 + (lane >> 2);
            const int colL = wn * 64 + n8 * 8 + (lane & 3) * 2;
            *(float2*)&C[(size_t)row0 * N + nBase + colL]       = make_float2(acc[mt][n8][0], acc[mt][n8][1]);
            *(float2*)&C[(size_t)(row0 + 8) * N + nBase + colL] = make_float2(acc[mt][n8][2], acc[mt][n8][3]);
            const float aS0 = s_att[0][colL], aS1 = s_att[0][colL + 1];
            const float aD0 = s_att[1][colL], aD1 = s_att[1][colL + 1];
            psS[mt * 2 + 0] += acc[mt][n8][0] * aS0 + acc[mt][n8][1] * aS1;
            psS[mt * 2 + 1] += acc[mt][n8][2] * aS0 + acc[mt][n8][3] * aS1;
            psD[mt * 2 + 0] += acc[mt][n8][0] * aD0 + acc[mt][n8][1] * aD1;
            psD[mt * 2 + 1] += acc[mt][n8][2] * aD0 + acc[mt][n8][3] * aD1;
        }
    }
#pragma unroll
    for (int o = 1; o <= 2; o <<= 1) {
#pragma unroll
        for (int k = 0; k < 4; k++) {
            psS[k] += __shfl_xor_sync(0xffffffffu, psS[k], o);
            psD[k] += __shfl_xor_sync(0xffffffffu, psD[k], o);
        }
    }
    if ((lane & 3) == 0) {
        const int q = lane >> 2;
#pragma unroll
        for (int mt = 0; mt < 2; mt++) {
            sredS[wn][wm * 32 + mt * 16 + q]     = psS[mt * 2 + 0];
            sredS[wn][wm * 32 + mt * 16 + q + 8] = psS[mt * 2 + 1];
            sredD[wn][wm * 32 + mt * 16 + q]     = psD[mt * 2 + 0];
            sredD[wn][wm * 32 + mt * 16 + q + 8] = psD[mt * 2 + 1];
        }
    }
    __syncthreads();
    if (tid < 128) {
        const int row = mBase + tid;
        g_as[row * HH + blockIdx.x] = sredS[0][tid] + sredS[1][tid];
        g_ad[row * HH + blockIdx.x] = sredD[0][tid] + sredD[1][tid];
    }
}

// ---------------- CSR build ----------------
__global__ void detect_kernel(const int* __restrict__ buf) {
    __shared__ int sh[256];
    int v = 0;
    for (int i = threadIdx.x; i < 8192; i += 256) v |= buf[2 * i + 1];
    sh[threadIdx.x] = v;
    __syncthreads();
    for (int s = 128; s > 0; s >>= 1) {
        if (threadIdx.x < s) sh[threadIdx.x] |= sh[threadIdx.x + s];
        __syncthreads();
    }
    if (threadIdx.x == 0) g_is64 = (sh[0] == 0) ? 1 : 0;
}

__global__ void zero_counts() {
    const int i = blockIdx.x * blockDim.x + threadIdx.x;
    if (i < NN) { g_deg[i] = 0; g_cur[i] = 0; }
}

__global__ void convert_kernel(const int* __restrict__ buf) {
    const int e = blockIdx.x * blockDim.x + threadIdx.x;
    if (e >= ETOT) return;
    int s, d;
    if (e >= EE) { s = d = e - EE; }
    else if (g_is64) { s = buf[2 * e]; d = buf[2 * (EE + e)]; }
    else             { s = buf[e];     d = buf[EE + e]; }
    g_src[e] = s; g_dst[e] = d;
    atomicAdd(&g_deg[d], 1);
}

__global__ void scan_blocks() {  // grid NBLK, block 256
    const int tid = threadIdx.x, lane = tid & 31, wid = tid >> 5;
    const int i = blockIdx.x * 256 + tid;
    const int v = g_deg[i];
    int x = v;
#pragma unroll
    for (int o = 1; o < 32; o <<= 1) {
        const int y = __shfl_up_sync(0xffffffffu, x, o);
        if (lane >= o) x += y;
    }
    __shared__ int ws[8], wsx[8];
    if (lane == 31) ws[wid] = x;
    __syncthreads();
    if (tid < 8) {
        int ex = 0;
        for (int k = 0; k < tid; k++) ex += ws[k];
        wsx[tid] = ex;
        if (tid == 7) g_bsum[blockIdx.x] = ex + ws[7];
    }
    __syncthreads();
    g_off[i] = wsx[wid] + (x - v);
}

__global__ void scan_bsum() {   // 1 block, 64 threads
    const int tid = threadIdx.x;
    const int v = g_bsum[tid];
    int x = v;
#pragma unroll
    for (int o = 1; o < 32; o <<= 1) {
        const int y = __shfl_up_sync(0xffffffffu, x, o);
        if ((tid & 31) >= o) x += y;
    }
    __shared__ int w0;
    if (tid == 31) w0 = x;
    __syncthreads();
    if (tid >= 32) x += w0;
    g_bsum[tid] = x - v;        // exclusive
    if (tid == 0) g_off[NN] = ETOT;
}

__global__ void scan_add() {    // grid NBLK, block 256
    const int i = blockIdx.x * 256 + threadIdx.x;
    g_off[i] += g_bsum[blockIdx.x];
}

__global__ void scatter_kernel() {
    const int e = blockIdx.x * blockDim.x + threadIdx.x;
    if (e >= ETOT) return;
    const int d = g_dst[e];
    const int pos = atomicAdd(&g_cur[d], 1);
    g_csrc[g_off[d] + pos] = g_src[e];
}

// ---------------- online softmax: warp per node, single pass ----------------
__global__ __launch_bounds__(128)
void csr_softmax_online() {
    const int warp = threadIdx.x >> 5, lane = threadIdx.x & 31;
    const int n = blockIdx.x * 4 + warp;
    const int off0 = g_off[n];
    const int deg  = g_off[n + 1] - off0;
    const float4 adp = *(const float4*)&g_ad[n * HH];
    float m0 = -1e30f, m1 = -1e30f, m2 = -1e30f, m3 = -1e30f;
    float s0 = 0.f, s1 = 0.f, s2 = 0.f, s3 = 0.f;
    for (int j = lane; j < deg; j += 32) {
        const int src = g_csrc[off0 + j];
        const float4 a = *(const float4*)&g_as[src * HH];
        const float x0 = lrelu(a.x + adp.x), x1 = lrelu(a.y + adp.y);
        const float x2 = lrelu(a.z + adp.z), x3 = lrelu(a.w + adp.w);
        *(float4*)&g_xw[(size_t)(off0 + j) * HH] = make_float4(x0, x1, x2, x3);
        if (x0 > m0) { s0 = s0 * __expf(m0 - x0) + 1.f; m0 = x0; } else s0 += __expf(x0 - m0);
        if (x1 > m1) { s1 = s1 * __expf(m1 - x1) + 1.f; m1 = x1; } else s1 += __expf(x1 - m1);
        if (x2 > m2) { s2 = s2 * __expf(m2 - x2) + 1.f; m2 = x2; } else s2 += __expf(x2 - m2);
        if (x3 > m3) { s3 = s3 * __expf(m3 - x3) + 1.f; m3 = x3; } else s3 += __expf(x3 - m3);
    }
    const float M0 = wmax(m0), M1 = wmax(m1), M2 = wmax(m2), M3 = wmax(m3);
    s0 *= __expf(m0 - M0); s1 *= __expf(m1 - M1);
    s2 *= __expf(m2 - M2); s3 *= __expf(m3 - M3);
    s0 = wsum(s0); s1 = wsum(s1); s2 = wsum(s2); s3 = wsum(s3);
    if (lane == 0) {
        *(float4*)&g_invden[n * HH] = make_float4(1.f / (s0 + 1e-16f), 1.f / (s1 + 1e-16f),
                                                  1.f / (s2 + 1e-16f), 1.f / (s3 + 1e-16f));
        *(float4*)&g_mx[n * HH] = make_float4(M0, M1, M2, M3);
    }
}

// ---------------- CSR aggregate: warp per (node, head) ----------------
// mode 0: elu(acc+bias) -> bf16 hi/lo split directly (layer 1 -> GEMM2 A operand)
// mode 1: dot(elu(acc+bias), p2w) -> red.add g_x2[n] (layer 2)
__global__ __launch_bounds__(256)
void csr_aggregate(const float* __restrict__ bias, const float* __restrict__ pw, int mode) {
    const int w = blockIdx.x * 8 + (threadIdx.x >> 5);
    const int lane = threadIdx.x & 31;
    const int n = w >> 2, h = w & 3;
    const int off0 = g_off[n];
    const int deg  = g_off[n + 1] - off0;
    const float invd = g_invden[n * HH + h];
    const float M    = g_mx[n * HH + h];
    float4 acc = make_float4(0.f, 0.f, 0.f, 0.f);
    for (int base = 0; base < deg; base += 32) {
        const int cnt = min(32, deg - base);
        int s = 0; float wgt = 0.f;
        if (lane < cnt) {
            const int slot = off0 + base + lane;
            s   = g_csrc[slot];
            wgt = __expf(g_xw[(size_t)slot * HH + h] - M) * invd;
        }
        for (int j = 0; j < cnt; j++) {
            const int   ss = __shfl_sync(0xffffffffu, s, j);
            const float ww = __shfl_sync(0xffffffffu, wgt, j);
            const float4 v = *(const float4*)&g_H[(size_t)ss * HC + h * CC + lane * 4];
            acc.x += v.x * ww; acc.y += v.y * ww; acc.z += v.z * ww; acc.w += v.w * ww;
        }
    }
    const float4 b4 = *(const float4*)&bias[h * CC + lane * 4];
    float4 v = make_float4(acc.x + b4.x, acc.y + b4.y, acc.z + b4.z, acc.w + b4.w);
    v.x = (v.x > 0.f) ? v.x : expm1f(v.x);
    v.y = (v.y > 0.f) ? v.y : expm1f(v.y);
    v.z = (v.z > 0.f) ? v.z : expm1f(v.z);
    v.w = (v.w > 0.f) ? v.w : expm1f(v.w);
    if (mode == 0) {
        const size_t idx = (size_t)n * HC + h * CC + lane * 4;
        const float h0 = __bfloat162float(__float2bfloat16(v.x));
        const float h1 = __bfloat162float(__float2bfloat16(v.y));
        const float h2 = __bfloat162float(__float2bfloat16(v.z));
        const float h3 = __bfloat162float(__float2bfloat16(v.w));
        *(uint2*)&g_Ahi[idx] = make_uint2(pack_bf2(v.x, v.y), pack_bf2(v.z, v.w));
        *(uint2*)&g_Alo[idx] = make_uint2(pack_bf2(v.x - h0, v.y - h1), pack_bf2(v.z - h2, v.w - h3));
    } else {
        const float4 p = *(const float4*)&pw[h * CC + lane * 4];
        float dot = v.x * p.x + v.y * p.y + v.z * p.z + v.w * p.w;
        dot = wsum(dot);
        if (lane == 0)
            asm volatile("red.global.add.f32 [%0], %1;" :: "l"(&g_x2[n]), "f"(dot) : "memory");
    }
}

// ---------------- x2 init ----------------
__global__ void x2_init(const float* __restrict__ p2b) {
    const int i = blockIdx.x * blockDim.x + threadIdx.x;
    if (i < BB * NODES) g_x2[i] = p2b[0];
}

// ---------------- layer norm ----------------
__global__ void ln_kernel(const float* __restrict__ g, const float* __restrict__ be,
                          float* __restrict__ out) {
    const int bb = blockIdx.x, tid = threadIdx.x;
    const int lane = tid & 31, wid = tid >> 5;
    float s = 0.f, s2 = 0.f;
    for (int i = tid; i < NODES; i += 256) {
        const float v = g_x2[bb * NODES + i];
        s += v; s2 += v * v;
    }
    s = wsum(s); s2 = wsum(s2);
    __shared__ float shs[8], shs2[8];
    if (lane == 0) { shs[wid] = s; shs2[wid] = s2; }
    __syncthreads();
    __shared__ float smu, srv;
    if (tid == 0) {
        float S = 0.f, S2 = 0.f;
        for (int w = 0; w < 8; w++) { S += shs[w]; S2 += shs2[w]; }
        const float mu = S / NODES;
        smu = mu;
        srv = rsqrtf(S2 / NODES - mu * mu + 1e-5f);
    }
    __syncthreads();
    const float mu = smu, rv = srv;
    for (int i = tid; i < NODES; i += 256) {
        const float v = (g_x2[bb * NODES + i] - mu) * rv * g[i] + be[i];
        out[bb * NODES + i] = v;
        g_x2[bb * NODES + i] = v;
    }
}

// ---------------- small FC ----------------
__global__ void fc_kernel(const float* __restrict__ in, const float* __restrict__ W,
                          const float* __restrict__ bias, float* __restrict__ out,
                          int Din, int Dout, int act) {
    const int j = blockIdx.x * blockDim.x + threadIdx.x;
    const int b = blockIdx.y;
    if (j >= Dout) return;
    const float* ir = in + (size_t)b * Din;
    float s = bias[j];
    for (int k = 0; k < Din; k++) s += ir[k] * W[(size_t)k * Dout + j];
    if (act) s = (s > 0.f) ? s : expm1f(s);
    out[b * Dout + j] = s;
}

// ---------------- final ----------------
__global__ void final_kernel(const float* __restrict__ lw, const float* __restrict__ lb,
                             float* __restrict__ out) {
    const int b = blockIdx.x, tid = threadIdx.x;
    const float v = g_e4[b * 64 + tid];
    out[BB * NODES + b * 64 + tid] = v;
    float p = v * lw[tid];
#pragma unroll
    for (int o = 16; o > 0; o >>= 1) p += __shfl_xor_sync(0xffffffffu, p, o);
    __shared__ float sh[2];
    if ((tid & 31) == 0) sh[tid >> 5] = p;
    __syncthreads();
    if (tid == 0) out[BB * NODES + BB * 64 + b] = sh[0] + sh[1] + lb[0];
}

// ---------------- launch ----------------
extern "C" void kernel_launch(void* const* d_in, const int* in_sizes, int n_in,
                              void* d_out, int out_size) {
    const float* x     = (const float*)d_in[0];
    const int*   eibuf = (const int*)d_in[1];
    const float* W1   = (const float*)d_in[3];
    const float* as1  = (const float*)d_in[4];
    const float* ad1  = (const float*)d_in[5];
    const float* b1   = (const float*)d_in[6];
    const float* W2   = (const float*)d_in[7];
    const float* as2  = (const float*)d_in[8];
    const float* ad2  = (const float*)d_in[9];
    const float* b2   = (const float*)d_in[10];
    const float* p2w  = (const float*)d_in[13];
    const float* p2b  = (const float*)d_in[14];
    const float* ln_g = (const float*)d_in[15];
    const float* ln_b = (const float*)d_in[16];
    const float* fw1  = (const float*)d_in[17];
    const float* fb1  = (const float*)d_in[18];
    const float* fw2  = (const float*)d_in[19];
    const float* fb2  = (const float*)d_in[20];
    const float* fw3  = (const float*)d_in[21];
    const float* fb3  = (const float*)d_in[22];
    const float* fw4  = (const float*)d_in[23];
    const float* fb4  = (const float*)d_in[24];
    const float* lw   = (const float*)d_in[25];
    const float* lb   = (const float*)d_in[26];
    float* out = (float*)d_out;

    float *pH, *px2, *pe1, *pe2, *pe3, *pe4;
    __nv_bfloat16 *pAhi, *pAlo, *pBhi, *pBlo;
    cudaGetSymbolAddress((void**)&pH,   g_H);
    cudaGetSymbolAddress((void**)&pAhi, g_Ahi);
    cudaGetSymbolAddress((void**)&pAlo, g_Alo);
    cudaGetSymbolAddress((void**)&pBhi, g_Bhi);
    cudaGetSymbolAddress((void**)&pBlo, g_Blo);
    cudaGetSymbolAddress((void**)&px2,  g_x2);
    cudaGetSymbolAddress((void**)&pe1,  g_e1);
    cudaGetSymbolAddress((void**)&pe2,  g_e2);
    cudaGetSymbolAddress((void**)&pe3,  g_e3);
    cudaGetSymbolAddress((void**)&pe4,  g_e4);

    cudaFuncSetAttribute(gemm_bf16split, cudaFuncAttributeMaxDynamicSharedMemorySize, 65536);

    const int eblocks = (ETOT + 255) / 256;
    const dim3 gemm_grid(HC / 128, NN / 128);

    // ===== CSR build =====
    detect_kernel<<<1, 256>>>(eibuf);
    zero_counts<<<NBLK, 256>>>();
    convert_kernel<<<eblocks, 256>>>(eibuf);
    scan_blocks<<<NBLK, 256>>>();
    scan_bsum<<<1, 64>>>();
    scan_add<<<NBLK, 256>>>();
    scatter_kernel<<<eblocks, 256>>>();

    // ===== GAT layer 1 =====
    split_kernel<<<(NN * DIN / 4) / 256, 256>>>(x, pAhi, pAlo);
    split_kernel<<<(DIN * HC / 4) / 256, 256>>>(W1, pBhi, pBlo);
    gemm_bf16split<<<gemm_grid, 256, 65536>>>(pAhi, pAlo, pBhi, pBlo, pH, NN, HC, DIN, as1, ad1);
    csr_softmax_online<<<NN / 4, 128>>>();
    csr_aggregate<<<NN * HH / 8, 256>>>(b1, nullptr, 0);   // writes bf16 split of h1

    // ===== GAT layer 2 =====
    split_kernel<<<(HC * HC / 4) / 256, 256>>>(W2, pBhi, pBlo);
    gemm_bf16split<<<gemm_grid, 256, 65536>>>(pAhi, pAlo, pBhi, pBlo, pH, NN, HC, HC, as2, ad2);
    csr_softmax_online<<<NN / 4, 128>>>();
    x2_init<<<(BB * NODES) / 256, 256>>>(p2b);
    csr_aggregate<<<NN * HH / 8, 256>>>(b2, p2w, 1);       // fused pool -> g_x2

    // ===== layer norm -> d_out[0:16384) =====
    ln_kernel<<<BB, 256>>>(ln_g, ln_b, out);

    // ===== encoder MLP =====
    fc_kernel<<<dim3(4, BB), 128>>>(px2, fw1, fb1, pe1, 1024, 512, 1);
    fc_kernel<<<dim3(2, BB), 128>>>(pe1, fw2, fb2, pe2, 512, 256, 1);
    fc_kernel<<<dim3(1, BB), 128>>>(pe2, fw3, fb3, pe3, 256, 128, 1);
    fc_kernel<<<dim3(1, BB), 128>>>(pe3, fw4, fb4, pe4, 128, 64, 1);
    final_kernel<<<BB, 64>>>(lw, lb, out);
}

// round 9
// speedup vs baseline: 1.8896x; 1.0213x over previous
#include <cuda_runtime.h>
#include <cuda_bf16.h>
#include <cstdint>
#include <cstddef>

// ---------------- problem constants ----------------
#define NN     16384
#define DIN    1024
#define HH     4
#define CC     128
#define HC     512
#define EE     262144
#define ETOT   (EE + NN)
#define BB     16
#define NODES  1024
#define NBLK   64

// ---------------- device scratch ----------------
__device__ float         g_H[(size_t)NN * HC];
__device__ __nv_bfloat16 g_Ahi[(size_t)NN * DIN];
__device__ __nv_bfloat16 g_Alo[(size_t)NN * DIN];
__device__ __nv_bfloat16 g_Bhi[DIN * HC];
__device__ __nv_bfloat16 g_Blo[DIN * HC];
__device__ float         g_as[NN * HH];
__device__ float         g_ad[NN * HH];
__device__ float         g_invden[NN * HH];
__device__ float         g_mx[NN * HH];
__device__ float         g_xw[(size_t)ETOT * HH];
__device__ int           g_src[ETOT];
__device__ int           g_dst[ETOT];
__device__ int           g_csrc[ETOT];
__device__ int           g_deg[NN];
__device__ int           g_cur[NN];
__device__ int           g_off[NN + 1];
__device__ int           g_bsum[NBLK];
__device__ int           g_is64;
__device__ float         g_x2[BB * NODES];
__device__ float         g_e1[BB * 512];
__device__ float         g_e2[BB * 256];
__device__ float         g_e3[BB * 128];
__device__ float         g_e4[BB * 64];

// ---------------- helpers ----------------
__device__ __forceinline__ float wsum(float v) {
#pragma unroll
    for (int o = 16; o > 0; o >>= 1) v += __shfl_xor_sync(0xffffffffu, v, o);
    return v;
}
__device__ __forceinline__ float wmax(float v) {
#pragma unroll
    for (int o = 16; o > 0; o >>= 1) v = fmaxf(v, __shfl_xor_sync(0xffffffffu, v, o));
    return v;
}
__device__ __forceinline__ float lrelu(float x) { return (x > 0.f) ? x : 0.2f * x; }
__device__ __forceinline__ void cp16(unsigned s, const void* g) {
    asm volatile("cp.async.cg.shared.global [%0], [%1], 16;" :: "r"(s), "l"(g));
}
__device__ __forceinline__ void ldsm4(unsigned* r, unsigned a) {
    asm volatile("ldmatrix.sync.aligned.m8n8.x4.shared.b16 {%0,%1,%2,%3}, [%4];"
                 : "=r"(r[0]), "=r"(r[1]), "=r"(r[2]), "=r"(r[3]) : "r"(a));
}
__device__ __forceinline__ void ldsm4t(unsigned* r, unsigned a) {
    asm volatile("ldmatrix.sync.aligned.m8n8.x4.trans.shared.b16 {%0,%1,%2,%3}, [%4];"
                 : "=r"(r[0]), "=r"(r[1]), "=r"(r[2]), "=r"(r[3]) : "r"(a));
}
__device__ __forceinline__ void mma16816(float* c, const unsigned* a, const unsigned* b) {
    asm volatile("mma.sync.aligned.m16n8k16.row.col.f32.bf16.bf16.f32 "
                 "{%0,%1,%2,%3}, {%4,%5,%6,%7}, {%8,%9}, {%0,%1,%2,%3};"
                 : "+f"(c[0]), "+f"(c[1]), "+f"(c[2]), "+f"(c[3])
                 : "r"(a[0]), "r"(a[1]), "r"(a[2]), "r"(a[3]), "r"(b[0]), "r"(b[1]));
}
__device__ __forceinline__ unsigned pack_bf2(float a, float b) {
    __nv_bfloat162 t = __halves2bfloat162(__float2bfloat16(a), __float2bfloat16(b));
    return *(unsigned*)&t;
}

// ---------------- fp32 -> bf16 hi/lo split ----------------
__global__ void split_kernel(const float* __restrict__ x, __nv_bfloat16* __restrict__ hi,
                             __nv_bfloat16* __restrict__ lo) {
    const size_t i = (size_t)blockIdx.x * blockDim.x + threadIdx.x;
    const float4 v = ((const float4*)x)[i];
    const float h0 = __bfloat162float(__float2bfloat16(v.x));
    const float h1 = __bfloat162float(__float2bfloat16(v.y));
    const float h2 = __bfloat162float(__float2bfloat16(v.z));
    const float h3 = __bfloat162float(__float2bfloat16(v.w));
    ((uint2*)hi)[i] = make_uint2(pack_bf2(v.x, v.y), pack_bf2(v.z, v.w));
    ((uint2*)lo)[i] = make_uint2(pack_bf2(v.x - h0, v.y - h1), pack_bf2(v.z - h2, v.w - h3));
}

// ---------------- bf16-split tensor GEMM + fused alpha dots ----------------
// 128x128x32 CTA tile, 8 warps (4x2, each 32x64), 3-stage cp.async pipeline.
// smem bytes: stage s in [0,3): Ahi at s*16384, Alo at +8192;
//             Bhi at 49152 + s*16384, Blo at +8192. Total 96 KB.
__global__ __launch_bounds__(256)
void gemm_bf16split(const __nv_bfloat16* __restrict__ Ahi, const __nv_bfloat16* __restrict__ Alo,
                    const __nv_bfloat16* __restrict__ Bhi, const __nv_bfloat16* __restrict__ Blo,
                    float* __restrict__ C, int M, int N, int K,
                    const float* __restrict__ attS, const float* __restrict__ attD) {
    extern __shared__ __nv_bfloat16 sm[];
    __shared__ float s_att[2][128];
    __shared__ float sredS[2][128], sredD[2][128];
    const int tid   = threadIdx.x;
    const int mBase = blockIdx.y * 128;
    const int nBase = blockIdx.x * 128;
    const unsigned sbase = (unsigned)__cvta_generic_to_shared(sm);

    if (tid < 128) {
        s_att[0][tid] = attS[nBase + tid];
        s_att[1][tid] = attD[nBase + tid];
    }

    const int wid = tid >> 5, lane = tid & 31;
    const int wm = wid & 3;
    const int wn = wid >> 2;

    float acc[2][8][4];
#pragma unroll
    for (int i = 0; i < 2; i++)
#pragma unroll
        for (int j = 0; j < 8; j++)
#pragma unroll
            for (int k = 0; k < 4; k++) acc[i][j][k] = 0.f;

    auto load_stage = [&](int stage, int kt) {
        const int kb = kt * 32;
        const unsigned aBase = sbase + stage * 16384;
        const unsigned bBase = sbase + 49152 + stage * 16384;
#pragma unroll
        for (int i = 0; i < 2; i++) {
            const int chunk = tid + (i << 8);
            const int row = chunk >> 2, u = chunk & 3;
            const int su = u ^ ((row >> 1) & 3);
            const size_t goff = (size_t)(mBase + row) * K + kb + u * 8;
            const unsigned s0 = aBase + row * 64 + su * 16;
            cp16(s0,        Ahi + goff);
            cp16(s0 + 8192, Alo + goff);
        }
#pragma unroll
        for (int i = 0; i < 2; i++) {
            const int chunk = tid + (i << 8);
            const int row = chunk >> 4, u = chunk & 15;
            const int su = u ^ (row & 7);
            const size_t goff = (size_t)(kb + row) * N + nBase + u * 8;
            const unsigned s0 = bBase + row * 256 + su * 16;
            cp16(s0,        Bhi + goff);
            cp16(s0 + 8192, Blo + goff);
        }
    };

    const int nk = K >> 5;
    load_stage(0, 0);
    asm volatile("cp.async.commit_group;");
    load_stage(1, 1);
    asm volatile("cp.async.commit_group;");

    for (int kt = 0; kt < nk; kt++) {
        const int stage = kt - (kt / 3) * 3;
        if (kt + 2 < nk) {
            const int ps = (kt + 2) - ((kt + 2) / 3) * 3;
            load_stage(ps, kt + 2);
        }
        asm volatile("cp.async.commit_group;");
        asm volatile("cp.async.wait_group 2;");
        __syncthreads();

        const unsigned aStage = sbase + stage * 16384;
        const unsigned bStage = sbase + 49152 + stage * 16384;
#pragma unroll
        for (int kk = 0; kk < 2; kk++) {
            unsigned ah[2][4], al[2][4], bh[4][4], bl[4][4];
#pragma unroll
            for (int mt = 0; mt < 2; mt++) {
                const int row = wm * 32 + mt * 16 + (lane & 15);
                const int u = (kk * 2 + (lane >> 4)) ^ ((row >> 1) & 3);
                const unsigned ad = aStage + row * 64 + u * 16;
                ldsm4(ah[mt], ad);
                ldsm4(al[mt], ad + 8192);
            }
#pragma unroll
            for (int nt = 0; nt < 4; nt++) {
                const int row = kk * 16 + (lane & 15);
                const int u = (wn * 8 + nt * 2 + (lane >> 4)) ^ (row & 7);
                const unsigned bd = bStage + row * 256 + u * 16;
                ldsm4t(bh[nt], bd);
                ldsm4t(bl[nt], bd + 8192);
            }
#pragma unroll
            for (int mt = 0; mt < 2; mt++)
#pragma unroll
                for (int n8 = 0; n8 < 8; n8++)
                    mma16816(acc[mt][n8], ah[mt], &bh[n8 >> 1][(n8 & 1) * 2]);
#pragma unroll
            for (int mt = 0; mt < 2; mt++)
#pragma unroll
                for (int n8 = 0; n8 < 8; n8++)
                    mma16816(acc[mt][n8], ah[mt], &bl[n8 >> 1][(n8 & 1) * 2]);
#pragma unroll
            for (int mt = 0; mt < 2; mt++)
#pragma unroll
                for (int n8 = 0; n8 < 8; n8++)
                    mma16816(acc[mt][n8], al[mt], &bh[n8 >> 1][(n8 & 1) * 2]);
        }
        __syncthreads();
    }

    // C store + fused alpha partials
    float psS[4] = {0.f, 0.f, 0.f, 0.f};
    float psD[4] = {0.f, 0.f, 0.f, 0.f};
#pragma unroll
    for (int mt = 0; mt < 2; mt++) {
#pragma unroll
        for (int n8 = 0; n8 < 8; n8++) {
            const int row0 = mBase + wm * 32 + mt * 16 + (lane >> 2);
            const int colL = wn * 64 + n8 * 8 + (lane & 3) * 2;
            *(float2*)&C[(size_t)row0 * N + nBase + colL]       = make_float2(acc[mt][n8][0], acc[mt][n8][1]);
            *(float2*)&C[(size_t)(row0 + 8) * N + nBase + colL] = make_float2(acc[mt][n8][2], acc[mt][n8][3]);
            const float aS0 = s_att[0][colL], aS1 = s_att[0][colL + 1];
            const float aD0 = s_att[1][colL], aD1 = s_att[1][colL + 1];
            psS[mt * 2 + 0] += acc[mt][n8][0] * aS0 + acc[mt][n8][1] * aS1;
            psS[mt * 2 + 1] += acc[mt][n8][2] * aS0 + acc[mt][n8][3] * aS1;
            psD[mt * 2 + 0] += acc[mt][n8][0] * aD0 + acc[mt][n8][1] * aD1;
            psD[mt * 2 + 1] += acc[mt][n8][2] * aD0 + acc[mt][n8][3] * aD1;
        }
    }
#pragma unroll
    for (int o = 1; o <= 2; o <<= 1) {
#pragma unroll
        for (int k = 0; k < 4; k++) {
            psS[k] += __shfl_xor_sync(0xffffffffu, psS[k], o);
            psD[k] += __shfl_xor_sync(0xffffffffu, psD[k], o);
        }
    }
    if ((lane & 3) == 0) {
        const int q = lane >> 2;
#pragma unroll
        for (int mt = 0; mt < 2; mt++) {
            sredS[wn][wm * 32 + mt * 16 + q]     = psS[mt * 2 + 0];
            sredS[wn][wm * 32 + mt * 16 + q + 8] = psS[mt * 2 + 1];
            sredD[wn][wm * 32 + mt * 16 + q]     = psD[mt * 2 + 0];
            sredD[wn][wm * 32 + mt * 16 + q + 8] = psD[mt * 2 + 1];
        }
    }
    __syncthreads();
    if (tid < 128) {
        const int row = mBase + tid;
        g_as[row * HH + blockIdx.x] = sredS[0][tid] + sredS[1][tid];
        g_ad[row * HH + blockIdx.x] = sredD[0][tid] + sredD[1][tid];
    }
}

// ---------------- CSR build ----------------
__global__ void detect_kernel(const int* __restrict__ buf) {
    __shared__ int sh[256];
    int v = 0;
    for (int i = threadIdx.x; i < 8192; i += 256) v |= buf[2 * i + 1];
    sh[threadIdx.x] = v;
    __syncthreads();
    for (int s = 128; s > 0; s >>= 1) {
        if (threadIdx.x < s) sh[threadIdx.x] |= sh[threadIdx.x + s];
        __syncthreads();
    }
    if (threadIdx.x == 0) g_is64 = (sh[0] == 0) ? 1 : 0;
}

__global__ void zero_counts() {
    const int i = blockIdx.x * blockDim.x + threadIdx.x;
    if (i < NN) { g_deg[i] = 0; g_cur[i] = 0; }
}

__global__ void convert_kernel(const int* __restrict__ buf) {
    const int e = blockIdx.x * blockDim.x + threadIdx.x;
    if (e >= ETOT) return;
    int s, d;
    if (e >= EE) { s = d = e - EE; }
    else if (g_is64) { s = buf[2 * e]; d = buf[2 * (EE + e)]; }
    else             { s = buf[e];     d = buf[EE + e]; }
    g_src[e] = s; g_dst[e] = d;
    atomicAdd(&g_deg[d], 1);
}

__global__ void scan_blocks() {
    const int tid = threadIdx.x, lane = tid & 31, wid = tid >> 5;
    const int i = blockIdx.x * 256 + tid;
    const int v = g_deg[i];
    int x = v;
#pragma unroll
    for (int o = 1; o < 32; o <<= 1) {
        const int y = __shfl_up_sync(0xffffffffu, x, o);
        if (lane >= o) x += y;
    }
    __shared__ int ws[8], wsx[8];
    if (lane == 31) ws[wid] = x;
    __syncthreads();
    if (tid < 8) {
        int ex = 0;
        for (int k = 0; k < tid; k++) ex += ws[k];
        wsx[tid] = ex;
        if (tid == 7) g_bsum[blockIdx.x] = ex + ws[7];
    }
    __syncthreads();
    g_off[i] = wsx[wid] + (x - v);
}

__global__ void scan_bsum() {
    const int tid = threadIdx.x;
    const int v = g_bsum[tid];
    int x = v;
#pragma unroll
    for (int o = 1; o < 32; o <<= 1) {
        const int y = __shfl_up_sync(0xffffffffu, x, o);
        if ((tid & 31) >= o) x += y;
    }
    __shared__ int w0;
    if (tid == 31) w0 = x;
    __syncthreads();
    if (tid >= 32) x += w0;
    g_bsum[tid] = x - v;
    if (tid == 0) g_off[NN] = ETOT;
}

__global__ void scan_add() {
    const int i = blockIdx.x * 256 + threadIdx.x;
    g_off[i] += g_bsum[blockIdx.x];
}

__global__ void scatter_kernel() {
    const int e = blockIdx.x * blockDim.x + threadIdx.x;
    if (e >= ETOT) return;
    const int d = g_dst[e];
    const int pos = atomicAdd(&g_cur[d], 1);
    g_csrc[g_off[d] + pos] = g_src[e];
}

// ---------------- online softmax: warp per node ----------------
__global__ __launch_bounds__(128)
void csr_softmax_online() {
    const int warp = threadIdx.x >> 5, lane = threadIdx.x & 31;
    const int n = blockIdx.x * 4 + warp;
    const int off0 = g_off[n];
    const int deg  = g_off[n + 1] - off0;
    const float4 adp = *(const float4*)&g_ad[n * HH];
    float m0 = -1e30f, m1 = -1e30f, m2 = -1e30f, m3 = -1e30f;
    float s0 = 0.f, s1 = 0.f, s2 = 0.f, s3 = 0.f;
    for (int j = lane; j < deg; j += 32) {
        const int src = g_csrc[off0 + j];
        const float4 a = *(const float4*)&g_as[src * HH];
        const float x0 = lrelu(a.x + adp.x), x1 = lrelu(a.y + adp.y);
        const float x2 = lrelu(a.z + adp.z), x3 = lrelu(a.w + adp.w);
        *(float4*)&g_xw[(size_t)(off0 + j) * HH] = make_float4(x0, x1, x2, x3);
        if (x0 > m0) { s0 = s0 * __expf(m0 - x0) + 1.f; m0 = x0; } else s0 += __expf(x0 - m0);
        if (x1 > m1) { s1 = s1 * __expf(m1 - x1) + 1.f; m1 = x1; } else s1 += __expf(x1 - m1);
        if (x2 > m2) { s2 = s2 * __expf(m2 - x2) + 1.f; m2 = x2; } else s2 += __expf(x2 - m2);
        if (x3 > m3) { s3 = s3 * __expf(m3 - x3) + 1.f; m3 = x3; } else s3 += __expf(x3 - m3);
    }
    const float M0 = wmax(m0), M1 = wmax(m1), M2 = wmax(m2), M3 = wmax(m3);
    s0 *= __expf(m0 - M0); s1 *= __expf(m1 - M1);
    s2 *= __expf(m2 - M2); s3 *= __expf(m3 - M3);
    s0 = wsum(s0); s1 = wsum(s1); s2 = wsum(s2); s3 = wsum(s3);
    if (lane == 0) {
        *(float4*)&g_invden[n * HH] = make_float4(1.f / (s0 + 1e-16f), 1.f / (s1 + 1e-16f),
                                                  1.f / (s2 + 1e-16f), 1.f / (s3 + 1e-16f));
        *(float4*)&g_mx[n * HH] = make_float4(M0, M1, M2, M3);
    }
}

// ---------------- CSR aggregate: warp per (node, head) ----------------
__global__ __launch_bounds__(256)
void csr_aggregate(const float* __restrict__ bias, const float* __restrict__ pw, int mode) {
    const int w = blockIdx.x * 8 + (threadIdx.x >> 5);
    const int lane = threadIdx.x & 31;
    const int n = w >> 2, h = w & 3;
    const int off0 = g_off[n];
    const int deg  = g_off[n + 1] - off0;
    const float invd = g_invden[n * HH + h];
    const float M    = g_mx[n * HH + h];
    float4 acc = make_float4(0.f, 0.f, 0.f, 0.f);
    for (int base = 0; base < deg; base += 32) {
        const int cnt = min(32, deg - base);
        int s = 0; float wgt = 0.f;
        if (lane < cnt) {
            const int slot = off0 + base + lane;
            s   = g_csrc[slot];
            wgt = __expf(g_xw[(size_t)slot * HH + h] - M) * invd;
        }
        for (int j = 0; j < cnt; j++) {
            const int   ss = __shfl_sync(0xffffffffu, s, j);
            const float ww = __shfl_sync(0xffffffffu, wgt, j);
            const float4 v = *(const float4*)&g_H[(size_t)ss * HC + h * CC + lane * 4];
            acc.x += v.x * ww; acc.y += v.y * ww; acc.z += v.z * ww; acc.w += v.w * ww;
        }
    }
    const float4 b4 = *(const float4*)&bias[h * CC + lane * 4];
    float4 v = make_float4(acc.x + b4.x, acc.y + b4.y, acc.z + b4.z, acc.w + b4.w);
    v.x = (v.x > 0.f) ? v.x : expm1f(v.x);
    v.y = (v.y > 0.f) ? v.y : expm1f(v.y);
    v.z = (v.z > 0.f) ? v.z : expm1f(v.z);
    v.w = (v.w > 0.f) ? v.w : expm1f(v.w);
    if (mode == 0) {
        const size_t idx = (size_t)n * HC + h * CC + lane * 4;
        const float h0 = __bfloat162float(__float2bfloat16(v.x));
        const float h1 = __bfloat162float(__float2bfloat16(v.y));
        const float h2 = __bfloat162float(__float2bfloat16(v.z));
        const float h3 = __bfloat162float(__float2bfloat16(v.w));
        *(uint2*)&g_Ahi[idx] = make_uint2(pack_bf2(v.x, v.y), pack_bf2(v.z, v.w));
        *(uint2*)&g_Alo[idx] = make_uint2(pack_bf2(v.x - h0, v.y - h1), pack_bf2(v.z - h2, v.w - h3));
    } else {
        const float4 p = *(const float4*)&pw[h * CC + lane * 4];
        float dot = v.x * p.x + v.y * p.y + v.z * p.z + v.w * p.w;
        dot = wsum(dot);
        if (lane == 0)
            asm volatile("red.global.add.f32 [%0], %1;" :: "l"(&g_x2[n]), "f"(dot) : "memory");
    }
}

// ---------------- x2 init ----------------
__global__ void x2_init(const float* __restrict__ p2b) {
    const int i = blockIdx.x * blockDim.x + threadIdx.x;
    if (i < BB * NODES) g_x2[i] = p2b[0];
}

// ---------------- layer norm ----------------
__global__ void ln_kernel(const float* __restrict__ g, const float* __restrict__ be,
                          float* __restrict__ out) {
    const int bb = blockIdx.x, tid = threadIdx.x;
    const int lane = tid & 31, wid = tid >> 5;
    float s = 0.f, s2 = 0.f;
    for (int i = tid; i < NODES; i += 256) {
        const float v = g_x2[bb * NODES + i];
        s += v; s2 += v * v;
    }
    s = wsum(s); s2 = wsum(s2);
    __shared__ float shs[8], shs2[8];
    if (lane == 0) { shs[wid] = s; shs2[wid] = s2; }
    __syncthreads();
    __shared__ float smu, srv;
    if (tid == 0) {
        float S = 0.f, S2 = 0.f;
        for (int w = 0; w < 8; w++) { S += shs[w]; S2 += shs2[w]; }
        const float mu = S / NODES;
        smu = mu;
        srv = rsqrtf(S2 / NODES - mu * mu + 1e-5f);
    }
    __syncthreads();
    const float mu = smu, rv = srv;
    for (int i = tid; i < NODES; i += 256) {
        const float v = (g_x2[bb * NODES + i] - mu) * rv * g[i] + be[i];
        out[bb * NODES + i] = v;
        g_x2[bb * NODES + i] = v;
    }
}

// ---------------- small FC ----------------
__global__ void fc_kernel(const float* __restrict__ in, const float* __restrict__ W,
                          const float* __restrict__ bias, float* __restrict__ out,
                          int Din, int Dout, int act) {
    const int j = blockIdx.x * blockDim.x + threadIdx.x;
    const int b = blockIdx.y;
    if (j >= Dout) return;
    const float* ir = in + (size_t)b * Din;
    float s = bias[j];
    for (int k = 0; k < Din; k++) s += ir[k] * W[(size_t)k * Dout + j];
    if (act) s = (s > 0.f) ? s : expm1f(s);
    out[b * Dout + j] = s;
}

// ---------------- final ----------------
__global__ void final_kernel(const float* __restrict__ lw, const float* __restrict__ lb,
                             float* __restrict__ out) {
    const int b = blockIdx.x, tid = threadIdx.x;
    const float v = g_e4[b * 64 + tid];
    out[BB * NODES + b * 64 + tid] = v;
    float p = v * lw[tid];
#pragma unroll
    for (int o = 16; o > 0; o >>= 1) p += __shfl_xor_sync(0xffffffffu, p, o);
    __shared__ float sh[2];
    if ((tid & 31) == 0) sh[tid >> 5] = p;
    __syncthreads();
    if (tid == 0) out[BB * NODES + BB * 64 + b] = sh[0] + sh[1] + lb[0];
}

// ---------------- launch ----------------
extern "C" void kernel_launch(void* const* d_in, const int* in_sizes, int n_in,
                              void* d_out, int out_size) {
    const float* x     = (const float*)d_in[0];
    const int*   eibuf = (const int*)d_in[1];
    const float* W1   = (const float*)d_in[3];
    const float* as1  = (const float*)d_in[4];
    const float* ad1  = (const float*)d_in[5];
    const float* b1   = (const float*)d_in[6];
    const float* W2   = (const float*)d_in[7];
    const float* as2  = (const float*)d_in[8];
    const float* ad2  = (const float*)d_in[9];
    const float* b2   = (const float*)d_in[10];
    const float* p2w  = (const float*)d_in[13];
    const float* p2b  = (const float*)d_in[14];
    const float* ln_g = (const float*)d_in[15];
    const float* ln_b = (const float*)d_in[16];
    const float* fw1  = (const float*)d_in[17];
    const float* fb1  = (const float*)d_in[18];
    const float* fw2  = (const float*)d_in[19];
    const float* fb2  = (const float*)d_in[20];
    const float* fw3  = (const float*)d_in[21];
    const float* fb3  = (const float*)d_in[22];
    const float* fw4  = (const float*)d_in[23];
    const float* fb4  = (const float*)d_in[24];
    const float* lw   = (const float*)d_in[25];
    const float* lb   = (const float*)d_in[26];
    float* out = (float*)d_out;

    float *pH, *px2, *pe1, *pe2, *pe3, *pe4;
    __nv_bfloat16 *pAhi, *pAlo, *pBhi, *pBlo;
    cudaGetSymbolAddress((void**)&pH,   g_H);
    cudaGetSymbolAddress((void**)&pAhi, g_Ahi);
    cudaGetSymbolAddress((void**)&pAlo, g_Alo);
    cudaGetSymbolAddress((void**)&pBhi, g_Bhi);
    cudaGetSymbolAddress((void**)&pBlo, g_Blo);
    cudaGetSymbolAddress((void**)&px2,  g_x2);
    cudaGetSymbolAddress((void**)&pe1,  g_e1);
    cudaGetSymbolAddress((void**)&pe2,  g_e2);
    cudaGetSymbolAddress((void**)&pe3,  g_e3);
    cudaGetSymbolAddress((void**)&pe4,  g_e4);

    cudaFuncSetAttribute(gemm_bf16split, cudaFuncAttributeMaxDynamicSharedMemorySize, 98304);

    const int eblocks = (ETOT + 255) / 256;
    const dim3 gemm_grid(HC / 128, NN / 128);

    // launch order: gemm_bf16split (layer 1) is launch index 5 for ncu -s 5
    split_kernel<<<(NN * DIN / 4) / 256, 256>>>(x, pAhi, pAlo);                 // 0
    split_kernel<<<(DIN * HC / 4) / 256, 256>>>(W1, pBhi, pBlo);                // 1
    detect_kernel<<<1, 256>>>(eibuf);                                           // 2
    zero_counts<<<NBLK, 256>>>();                                               // 3
    convert_kernel<<<eblocks, 256>>>(eibuf);                                    // 4
    gemm_bf16split<<<gemm_grid, 256, 98304>>>(pAhi, pAlo, pBhi, pBlo, pH,
                                              NN, HC, DIN, as1, ad1);           // 5
    scan_blocks<<<NBLK, 256>>>();
    scan_bsum<<<1, 64>>>();
    scan_add<<<NBLK, 256>>>();
    scatter_kernel<<<eblocks, 256>>>();
    csr_softmax_online<<<NN / 4, 128>>>();
    csr_aggregate<<<NN * HH / 8, 256>>>(b1, nullptr, 0);   // writes bf16 split of h1

    // ===== GAT layer 2 =====
    split_kernel<<<(HC * HC / 4) / 256, 256>>>(W2, pBhi, pBlo);
    gemm_bf16split<<<gemm_grid, 256, 98304>>>(pAhi, pAlo, pBhi, pBlo, pH,
                                              NN, HC, HC, as2, ad2);
    csr_softmax_online<<<NN / 4, 128>>>();
    x2_init<<<(BB * NODES) / 256, 256>>>(p2b);
    csr_aggregate<<<NN * HH / 8, 256>>>(b2, p2w, 1);       // fused pool -> g_x2

    // ===== layer norm -> d_out[0:16384) =====
    ln_kernel<<<BB, 256>>>(ln_g, ln_b, out);

    // ===== encoder MLP =====
    fc_kernel<<<dim3(4, BB), 128>>>(px2, fw1, fb1, pe1, 1024, 512, 1);
    fc_kernel<<<dim3(2, BB), 128>>>(pe1, fw2, fb2, pe2, 512, 256, 1);
    fc_kernel<<<dim3(1, BB), 128>>>(pe2, fw3, fb3, pe3, 256, 128, 1);
    fc_kernel<<<dim3(1, BB), 128>>>(pe3, fw4, fb4, pe4, 128, 64, 1);
    final_kernel<<<BB, 64>>>(lw, lb, out);
}

// round 10
// speedup vs baseline: 2.5295x; 1.3386x over previous
#include <cuda_runtime.h>
#include <cuda_fp16.h>
#include <cstdint>
#include <cstddef>

// ---------------- problem constants ----------------
#define NN     16384
#define DIN    1024
#define HH     4
#define CC     128
#define HC     512
#define EE     262144
#define ETOT   (EE + NN)
#define BB     16
#define NODES  1024
#define NBLK   64

// ---------------- device scratch ----------------
__device__ float  g_H[(size_t)NN * HC];
__device__ __half g_Af[(size_t)NN * DIN];
__device__ __half g_Bf[DIN * HC];
__device__ float  g_as[NN * HH];
__device__ float  g_ad[NN * HH];
__device__ float  g_invden[NN * HH];
__device__ float  g_mx[NN * HH];
__device__ float  g_xw[(size_t)ETOT * HH];
__device__ int    g_src[ETOT];
__device__ int    g_dst[ETOT];
__device__ int    g_csrc[ETOT];
__device__ int    g_deg[NN];
__device__ int    g_cur[NN];
__device__ int    g_off[NN + 1];
__device__ int    g_bsum[NBLK];
__device__ int    g_is64;
__device__ float  g_x2[BB * NODES];
__device__ float  g_e1[BB * 512];
__device__ float  g_e2[BB * 256];
__device__ float  g_e3[BB * 128];
__device__ float  g_e4[BB * 64];

// ---------------- helpers ----------------
__device__ __forceinline__ float wsum(float v) {
#pragma unroll
    for (int o = 16; o > 0; o >>= 1) v += __shfl_xor_sync(0xffffffffu, v, o);
    return v;
}
__device__ __forceinline__ float wmax(float v) {
#pragma unroll
    for (int o = 16; o > 0; o >>= 1) v = fmaxf(v, __shfl_xor_sync(0xffffffffu, v, o));
    return v;
}
__device__ __forceinline__ float lrelu(float x) { return (x > 0.f) ? x : 0.2f * x; }
__device__ __forceinline__ void cp16(unsigned s, const void* g) {
    asm volatile("cp.async.cg.shared.global [%0], [%1], 16;" :: "r"(s), "l"(g));
}
__device__ __forceinline__ void ldsm4(unsigned* r, unsigned a) {
    asm volatile("ldmatrix.sync.aligned.m8n8.x4.shared.b16 {%0,%1,%2,%3}, [%4];"
                 : "=r"(r[0]), "=r"(r[1]), "=r"(r[2]), "=r"(r[3]) : "r"(a));
}
__device__ __forceinline__ void ldsm4t(unsigned* r, unsigned a) {
    asm volatile("ldmatrix.sync.aligned.m8n8.x4.trans.shared.b16 {%0,%1,%2,%3}, [%4];"
                 : "=r"(r[0]), "=r"(r[1]), "=r"(r[2]), "=r"(r[3]) : "r"(a));
}
__device__ __forceinline__ void mma16816(float* c, const unsigned* a, const unsigned* b) {
    asm volatile("mma.sync.aligned.m16n8k16.row.col.f32.f16.f16.f32 "
                 "{%0,%1,%2,%3}, {%4,%5,%6,%7}, {%8,%9}, {%0,%1,%2,%3};"
                 : "+f"(c[0]), "+f"(c[1]), "+f"(c[2]), "+f"(c[3])
                 : "r"(a[0]), "r"(a[1]), "r"(a[2]), "r"(a[3]), "r"(b[0]), "r"(b[1]));
}
__device__ __forceinline__ unsigned pack_h2(float a, float b) {
    __half2 t = __floats2half2_rn(a, b);
    return *(unsigned*)&t;
}

// ---------------- fp32 -> fp16 convert ----------------
__global__ void cvt_kernel(const float* __restrict__ x, __half* __restrict__ o) {
    const size_t i = (size_t)blockIdx.x * blockDim.x + threadIdx.x;
    const float4 v = ((const float4*)x)[i];
    ((uint2*)o)[i] = make_uint2(pack_h2(v.x, v.y), pack_h2(v.z, v.w));
}

// ---------------- fp16 tensor GEMM + fused alpha dots ----------------
// 128x128x32 CTA tile, 8 warps (4x2, each 32x64), 4-stage cp.async pipeline.
// smem: stage s in [0,4): A at s*8192 (128 rows x 64B), B at 32768 + s*8192 (32 rows x 256B).
__global__ __launch_bounds__(256)
void gemm_fp16(const __half* __restrict__ A, const __half* __restrict__ B,
               float* __restrict__ C, int M, int N, int K,
               const float* __restrict__ attS, const float* __restrict__ attD) {
    extern __shared__ __half sm[];
    __shared__ float s_att[2][128];
    __shared__ float sredS[2][128], sredD[2][128];
    const int tid   = threadIdx.x;
    const int mBase = blockIdx.y * 128;
    const int nBase = blockIdx.x * 128;
    const unsigned sbase = (unsigned)__cvta_generic_to_shared(sm);

    if (tid < 128) {
        s_att[0][tid] = attS[nBase + tid];
        s_att[1][tid] = attD[nBase + tid];
    }

    const int wid = tid >> 5, lane = tid & 31;
    const int wm = wid & 3;
    const int wn = wid >> 2;

    float acc[2][8][4];
#pragma unroll
    for (int i = 0; i < 2; i++)
#pragma unroll
        for (int j = 0; j < 8; j++)
#pragma unroll
            for (int k = 0; k < 4; k++) acc[i][j][k] = 0.f;

    auto load_stage = [&](int stage, int kt) {
        const int kb = kt * 32;
        const unsigned aBase = sbase + stage * 8192;
        const unsigned bBase = sbase + 32768 + stage * 8192;
#pragma unroll
        for (int i = 0; i < 2; i++) {
            const int chunk = tid + (i << 8);
            const int row = chunk >> 2, u = chunk & 3;
            const int su = u ^ ((row >> 1) & 3);
            cp16(aBase + row * 64 + su * 16, A + (size_t)(mBase + row) * K + kb + u * 8);
        }
#pragma unroll
        for (int i = 0; i < 2; i++) {
            const int chunk = tid + (i << 8);
            const int row = chunk >> 4, u = chunk & 15;
            const int su = u ^ (row & 7);
            cp16(bBase + row * 256 + su * 16, B + (size_t)(kb + row) * N + nBase + u * 8);
        }
    };

    const int nk = K >> 5;
    load_stage(0, 0);
    asm volatile("cp.async.commit_group;");
    load_stage(1, 1);
    asm volatile("cp.async.commit_group;");
    load_stage(2, 2);
    asm volatile("cp.async.commit_group;");

    for (int kt = 0; kt < nk; kt++) {
        if (kt + 3 < nk) load_stage((kt + 3) & 3, kt + 3);
        asm volatile("cp.async.commit_group;");
        asm volatile("cp.async.wait_group 3;");
        __syncthreads();

        const int stage = kt & 3;
        const unsigned aStage = sbase + stage * 8192;
        const unsigned bStage = sbase + 32768 + stage * 8192;
#pragma unroll
        for (int kk = 0; kk < 2; kk++) {
            unsigned ah[2][4], bh[4][4];
#pragma unroll
            for (int mt = 0; mt < 2; mt++) {
                const int row = wm * 32 + mt * 16 + (lane & 15);
                const int u = (kk * 2 + (lane >> 4)) ^ ((row >> 1) & 3);
                ldsm4(ah[mt], aStage + row * 64 + u * 16);
            }
#pragma unroll
            for (int nt = 0; nt < 4; nt++) {
                const int row = kk * 16 + (lane & 15);
                const int u = (wn * 8 + nt * 2 + (lane >> 4)) ^ (row & 7);
                ldsm4t(bh[nt], bStage + row * 256 + u * 16);
            }
#pragma unroll
            for (int mt = 0; mt < 2; mt++)
#pragma unroll
                for (int n8 = 0; n8 < 8; n8++)
                    mma16816(acc[mt][n8], ah[mt], &bh[n8 >> 1][(n8 & 1) * 2]);
        }
        __syncthreads();
    }

    // C store + fused alpha partials
    float psS[4] = {0.f, 0.f, 0.f, 0.f};
    float psD[4] = {0.f, 0.f, 0.f, 0.f};
#pragma unroll
    for (int mt = 0; mt < 2; mt++) {
#pragma unroll
        for (int n8 = 0; n8 < 8; n8++) {
            const int row0 = mBase + wm * 32 + mt * 16 + (lane >> 2);
            const int colL = wn * 64 + n8 * 8 + (lane & 3) * 2;
            *(float2*)&C[(size_t)row0 * N + nBase + colL]       = make_float2(acc[mt][n8][0], acc[mt][n8][1]);
            *(float2*)&C[(size_t)(row0 + 8) * N + nBase + colL] = make_float2(acc[mt][n8][2], acc[mt][n8][3]);
            const float aS0 = s_att[0][colL], aS1 = s_att[0][colL + 1];
            const float aD0 = s_att[1][colL], aD1 = s_att[1][colL + 1];
            psS[mt * 2 + 0] += acc[mt][n8][0] * aS0 + acc[mt][n8][1] * aS1;
            psS[mt * 2 + 1] += acc[mt][n8][2] * aS0 + acc[mt][n8][3] * aS1;
            psD[mt * 2 + 0] += acc[mt][n8][0] * aD0 + acc[mt][n8][1] * aD1;
            psD[mt * 2 + 1] += acc[mt][n8][2] * aD0 + acc[mt][n8][3] * aD1;
        }
    }
#pragma unroll
    for (int o = 1; o <= 2; o <<= 1) {
#pragma unroll
        for (int k = 0; k < 4; k++) {
            psS[k] += __shfl_xor_sync(0xffffffffu, psS[k], o);
            psD[k] += __shfl_xor_sync(0xffffffffu, psD[k], o);
        }
    }
    if ((lane & 3) == 0) {
        const int q = lane >> 2;
#pragma unroll
        for (int mt = 0; mt < 2; mt++) {
            sredS[wn][wm * 32 + mt * 16 + q]     = psS[mt * 2 + 0];
            sredS[wn][wm * 32 + mt * 16 + q + 8] = psS[mt * 2 + 1];
            sredD[wn][wm * 32 + mt * 16 + q]     = psD[mt * 2 + 0];
            sredD[wn][wm * 32 + mt * 16 + q + 8] = psD[mt * 2 + 1];
        }
    }
    __syncthreads();
    if (tid < 128) {
        const int row = mBase + tid;
        g_as[row * HH + blockIdx.x] = sredS[0][tid] + sredS[1][tid];
        g_ad[row * HH + blockIdx.x] = sredD[0][tid] + sredD[1][tid];
    }
}

// ---------------- CSR build ----------------
__global__ void detect_kernel(const int* __restrict__ buf) {
    __shared__ int sh[256];
    int v = 0;
    for (int i = threadIdx.x; i < 8192; i += 256) v |= buf[2 * i + 1];
    sh[threadIdx.x] = v;
    __syncthreads();
    for (int s = 128; s > 0; s >>= 1) {
        if (threadIdx.x < s) sh[threadIdx.x] |= sh[threadIdx.x + s];
        __syncthreads();
    }
    if (threadIdx.x == 0) g_is64 = (sh[0] == 0) ? 1 : 0;
}

__global__ void zero_counts() {
    const int i = blockIdx.x * blockDim.x + threadIdx.x;
    if (i < NN) { g_deg[i] = 0; g_cur[i] = 0; }
}

__global__ void convert_kernel(const int* __restrict__ buf) {
    const int e = blockIdx.x * blockDim.x + threadIdx.x;
    if (e >= ETOT) return;
    int s, d;
    if (e >= EE) { s = d = e - EE; }
    else if (g_is64) { s = buf[2 * e]; d = buf[2 * (EE + e)]; }
    else             { s = buf[e];     d = buf[EE + e]; }
    g_src[e] = s; g_dst[e] = d;
    atomicAdd(&g_deg[d], 1);
}

__global__ void scan_blocks() {
    const int tid = threadIdx.x, lane = tid & 31, wid = tid >> 5;
    const int i = blockIdx.x * 256 + tid;
    const int v = g_deg[i];
    int x = v;
#pragma unroll
    for (int o = 1; o < 32; o <<= 1) {
        const int y = __shfl_up_sync(0xffffffffu, x, o);
        if (lane >= o) x += y;
    }
    __shared__ int ws[8], wsx[8];
    if (lane == 31) ws[wid] = x;
    __syncthreads();
    if (tid < 8) {
        int ex = 0;
        for (int k = 0; k < tid; k++) ex += ws[k];
        wsx[tid] = ex;
        if (tid == 7) g_bsum[blockIdx.x] = ex + ws[7];
    }
    __syncthreads();
    g_off[i] = wsx[wid] + (x - v);
}

__global__ void scan_bsum() {
    const int tid = threadIdx.x;
    const int v = g_bsum[tid];
    int x = v;
#pragma unroll
    for (int o = 1; o < 32; o <<= 1) {
        const int y = __shfl_up_sync(0xffffffffu, x, o);
        if ((tid & 31) >= o) x += y;
    }
    __shared__ int w0;
    if (tid == 31) w0 = x;
    __syncthreads();
    if (tid >= 32) x += w0;
    g_bsum[tid] = x - v;
    if (tid == 0) g_off[NN] = ETOT;
}

__global__ void scan_add() {
    const int i = blockIdx.x * 256 + threadIdx.x;
    g_off[i] += g_bsum[blockIdx.x];
}

__global__ void scatter_kernel() {
    const int e = blockIdx.x * blockDim.x + threadIdx.x;
    if (e >= ETOT) return;
    const int d = g_dst[e];
    const int pos = atomicAdd(&g_cur[d], 1);
    g_csrc[g_off[d] + pos] = g_src[e];
}

// ---------------- online softmax: warp per node ----------------
__global__ __launch_bounds__(128)
void csr_softmax_online() {
    const int warp = threadIdx.x >> 5, lane = threadIdx.x & 31;
    const int n = blockIdx.x * 4 + warp;
    const int off0 = g_off[n];
    const int deg  = g_off[n + 1] - off0;
    const float4 adp = *(const float4*)&g_ad[n * HH];
    float m0 = -1e30f, m1 = -1e30f, m2 = -1e30f, m3 = -1e30f;
    float s0 = 0.f, s1 = 0.f, s2 = 0.f, s3 = 0.f;
    for (int j = lane; j < deg; j += 32) {
        const int src = g_csrc[off0 + j];
        const float4 a = *(const float4*)&g_as[src * HH];
        const float x0 = lrelu(a.x + adp.x), x1 = lrelu(a.y + adp.y);
        const float x2 = lrelu(a.z + adp.z), x3 = lrelu(a.w + adp.w);
        *(float4*)&g_xw[(size_t)(off0 + j) * HH] = make_float4(x0, x1, x2, x3);
        if (x0 > m0) { s0 = s0 * __expf(m0 - x0) + 1.f; m0 = x0; } else s0 += __expf(x0 - m0);
        if (x1 > m1) { s1 = s1 * __expf(m1 - x1) + 1.f; m1 = x1; } else s1 += __expf(x1 - m1);
        if (x2 > m2) { s2 = s2 * __expf(m2 - x2) + 1.f; m2 = x2; } else s2 += __expf(x2 - m2);
        if (x3 > m3) { s3 = s3 * __expf(m3 - x3) + 1.f; m3 = x3; } else s3 += __expf(x3 - m3);
    }
    const float M0 = wmax(m0), M1 = wmax(m1), M2 = wmax(m2), M3 = wmax(m3);
    s0 *= __expf(m0 - M0); s1 *= __expf(m1 - M1);
    s2 *= __expf(m2 - M2); s3 *= __expf(m3 - M3);
    s0 = wsum(s0); s1 = wsum(s1); s2 = wsum(s2); s3 = wsum(s3);
    if (lane == 0) {
        *(float4*)&g_invden[n * HH] = make_float4(1.f / (s0 + 1e-16f), 1.f / (s1 + 1e-16f),
                                                  1.f / (s2 + 1e-16f), 1.f / (s3 + 1e-16f));
        *(float4*)&g_mx[n * HH] = make_float4(M0, M1, M2, M3);
    }
}

// ---------------- CSR aggregate: warp per (node, head) ----------------
// mode 0: elu(acc+bias) -> fp16 g_Af (layer 1 -> GEMM2 A operand)
// mode 1: dot(elu(acc+bias), p2w) -> red.add g_x2[n] (layer 2)
__global__ __launch_bounds__(256)
void csr_aggregate(const float* __restrict__ bias, const float* __restrict__ pw, int mode) {
    const int w = blockIdx.x * 8 + (threadIdx.x >> 5);
    const int lane = threadIdx.x & 31;
    const int n = w >> 2, h = w & 3;
    const int off0 = g_off[n];
    const int deg  = g_off[n + 1] - off0;
    const float invd = g_invden[n * HH + h];
    const float M    = g_mx[n * HH + h];
    float4 acc = make_float4(0.f, 0.f, 0.f, 0.f);
    for (int base = 0; base < deg; base += 32) {
        const int cnt = min(32, deg - base);
        int s = 0; float wgt = 0.f;
        if (lane < cnt) {
            const int slot = off0 + base + lane;
            s   = g_csrc[slot];
            wgt = __expf(g_xw[(size_t)slot * HH + h] - M) * invd;
        }
        for (int j = 0; j < cnt; j++) {
            const int   ss = __shfl_sync(0xffffffffu, s, j);
            const float ww = __shfl_sync(0xffffffffu, wgt, j);
            const float4 v = *(const float4*)&g_H[(size_t)ss * HC + h * CC + lane * 4];
            acc.x += v.x * ww; acc.y += v.y * ww; acc.z += v.z * ww; acc.w += v.w * ww;
        }
    }
    const float4 b4 = *(const float4*)&bias[h * CC + lane * 4];
    float4 v = make_float4(acc.x + b4.x, acc.y + b4.y, acc.z + b4.z, acc.w + b4.w);
    v.x = (v.x > 0.f) ? v.x : expm1f(v.x);
    v.y = (v.y > 0.f) ? v.y : expm1f(v.y);
    v.z = (v.z > 0.f) ? v.z : expm1f(v.z);
    v.w = (v.w > 0.f) ? v.w : expm1f(v.w);
    if (mode == 0) {
        const size_t idx = (size_t)n * HC + h * CC + lane * 4;
        *(uint2*)&g_Af[idx] = make_uint2(pack_h2(v.x, v.y), pack_h2(v.z, v.w));
    } else {
        const float4 p = *(const float4*)&pw[h * CC + lane * 4];
        float dot = v.x * p.x + v.y * p.y + v.z * p.z + v.w * p.w;
        dot = wsum(dot);
        if (lane == 0)
            asm volatile("red.global.add.f32 [%0], %1;" :: "l"(&g_x2[n]), "f"(dot) : "memory");
    }
}

// ---------------- x2 init ----------------
__global__ void x2_init(const float* __restrict__ p2b) {
    const int i = blockIdx.x * blockDim.x + threadIdx.x;
    if (i < BB * NODES) g_x2[i] = p2b[0];
}

// ---------------- layer norm ----------------
__global__ void ln_kernel(const float* __restrict__ g, const float* __restrict__ be,
                          float* __restrict__ out) {
    const int bb = blockIdx.x, tid = threadIdx.x;
    const int lane = tid & 31, wid = tid >> 5;
    float s = 0.f, s2 = 0.f;
    for (int i = tid; i < NODES; i += 256) {
        const float v = g_x2[bb * NODES + i];
        s += v; s2 += v * v;
    }
    s = wsum(s); s2 = wsum(s2);
    __shared__ float shs[8], shs2[8];
    if (lane == 0) { shs[wid] = s; shs2[wid] = s2; }
    __syncthreads();
    __shared__ float smu, srv;
    if (tid == 0) {
        float S = 0.f, S2 = 0.f;
        for (int w = 0; w < 8; w++) { S += shs[w]; S2 += shs2[w]; }
        const float mu = S / NODES;
        smu = mu;
        srv = rsqrtf(S2 / NODES - mu * mu + 1e-5f);
    }
    __syncthreads();
    const float mu = smu, rv = srv;
    for (int i = tid; i < NODES; i += 256) {
        const float v = (g_x2[bb * NODES + i] - mu) * rv * g[i] + be[i];
        out[bb * NODES + i] = v;
        g_x2[bb * NODES + i] = v;
    }
}

// ---------------- small FC ----------------
__global__ void fc_kernel(const float* __restrict__ in, const float* __restrict__ W,
                          const float* __restrict__ bias, float* __restrict__ out,
                          int Din, int Dout, int act) {
    const int j = blockIdx.x * blockDim.x + threadIdx.x;
    const int b = blockIdx.y;
    if (j >= Dout) return;
    const float* ir = in + (size_t)b * Din;
    float s = bias[j];
    for (int k = 0; k < Din; k++) s += ir[k] * W[(size_t)k * Dout + j];
    if (act) s = (s > 0.f) ? s : expm1f(s);
    out[b * Dout + j] = s;
}

// ---------------- final ----------------
__global__ void final_kernel(const float* __restrict__ lw, const float* __restrict__ lb,
                             float* __restrict__ out) {
    const int b = blockIdx.x, tid = threadIdx.x;
    const float v = g_e4[b * 64 + tid];
    out[BB * NODES + b * 64 + tid] = v;
    float p = v * lw[tid];
#pragma unroll
    for (int o = 16; o > 0; o >>= 1) p += __shfl_xor_sync(0xffffffffu, p, o);
    __shared__ float sh[2];
    if ((tid & 31) == 0) sh[tid >> 5] = p;
    __syncthreads();
    if (tid == 0) out[BB * NODES + BB * 64 + b] = sh[0] + sh[1] + lb[0];
}

// ---------------- launch ----------------
extern "C" void kernel_launch(void* const* d_in, const int* in_sizes, int n_in,
                              void* d_out, int out_size) {
    const float* x     = (const float*)d_in[0];
    const int*   eibuf = (const int*)d_in[1];
    const float* W1   = (const float*)d_in[3];
    const float* as1  = (const float*)d_in[4];
    const float* ad1  = (const float*)d_in[5];
    const float* b1   = (const float*)d_in[6];
    const float* W2   = (const float*)d_in[7];
    const float* as2  = (const float*)d_in[8];
    const float* ad2  = (const float*)d_in[9];
    const float* b2   = (const float*)d_in[10];
    const float* p2w  = (const float*)d_in[13];
    const float* p2b  = (const float*)d_in[14];
    const float* ln_g = (const float*)d_in[15];
    const float* ln_b = (const float*)d_in[16];
    const float* fw1  = (const float*)d_in[17];
    const float* fb1  = (const float*)d_in[18];
    const float* fw2  = (const float*)d_in[19];
    const float* fb2  = (const float*)d_in[20];
    const float* fw3  = (const float*)d_in[21];
    const float* fb3  = (const float*)d_in[22];
    const float* fw4  = (const float*)d_in[23];
    const float* fb4  = (const float*)d_in[24];
    const float* lw   = (const float*)d_in[25];
    const float* lb   = (const float*)d_in[26];
    float* out = (float*)d_out;

    float *pH, *px2, *pe1, *pe2, *pe3, *pe4;
    __half *pAf, *pBf;
    cudaGetSymbolAddress((void**)&pH,  g_H);
    cudaGetSymbolAddress((void**)&pAf, g_Af);
    cudaGetSymbolAddress((void**)&pBf, g_Bf);
    cudaGetSymbolAddress((void**)&px2, g_x2);
    cudaGetSymbolAddress((void**)&pe1, g_e1);
    cudaGetSymbolAddress((void**)&pe2, g_e2);
    cudaGetSymbolAddress((void**)&pe3, g_e3);
    cudaGetSymbolAddress((void**)&pe4, g_e4);

    cudaFuncSetAttribute(gemm_fp16, cudaFuncAttributeMaxDynamicSharedMemorySize, 65536);

    const int eblocks = (ETOT + 255) / 256;
    const dim3 gemm_grid(HC / 128, NN / 128);

    // launch order: gemm_fp16 (layer 1) is launch index 5 for ncu -s 5
    cvt_kernel<<<(NN * DIN / 4) / 256, 256>>>(x, pAf);                          // 0
    cvt_kernel<<<(DIN * HC / 4) / 256, 256>>>(W1, pBf);                         // 1
    detect_kernel<<<1, 256>>>(eibuf);                                           // 2
    zero_counts<<<NBLK, 256>>>();                                               // 3
    convert_kernel<<<eblocks, 256>>>(eibuf);                                    // 4
    gemm_fp16<<<gemm_grid, 256, 65536>>>(pAf, pBf, pH, NN, HC, DIN, as1, ad1);  // 5
    scan_blocks<<<NBLK, 256>>>();
    scan_bsum<<<1, 64>>>();
    scan_add<<<NBLK, 256>>>();
    scatter_kernel<<<eblocks, 256>>>();
    csr_softmax_online<<<NN / 4, 128>>>();
    csr_aggregate<<<NN * HH / 8, 256>>>(b1, nullptr, 0);   // writes fp16 h1

    // ===== GAT layer 2 =====
    cvt_kernel<<<(HC * HC / 4) / 256, 256>>>(W2, pBf);
    gemm_fp16<<<gemm_grid, 256, 65536>>>(pAf, pBf, pH, NN, HC, HC, as2, ad2);
    csr_softmax_online<<<NN / 4, 128>>>();
    x2_init<<<(BB * NODES) / 256, 256>>>(p2b);
    csr_aggregate<<<NN * HH / 8, 256>>>(b2, p2w, 1);       // fused pool -> g_x2

    // ===== layer norm -> d_out[0:16384) =====
    ln_kernel<<<BB, 256>>>(ln_g, ln_b, out);

    // ===== encoder MLP =====
    fc_kernel<<<dim3(4, BB), 128>>>(px2, fw1, fb1, pe1, 1024, 512, 1);
    fc_kernel<<<dim3(2, BB), 128>>>(pe1, fw2, fb2, pe2, 512, 256, 1);
    fc_kernel<<<dim3(1, BB), 128>>>(pe2, fw3, fb3, pe3, 256, 128, 1);
    fc_kernel<<<dim3(1, BB), 128>>>(pe3, fw4, fb4, pe4, 128, 64, 1);
    final_kernel<<<BB, 64>>>(lw, lb, out);
}

// round 11
// speedup vs baseline: 2.6832x; 1.0608x over previous
#include <cuda_runtime.h>
#include <cuda_fp16.h>
#include <cstdint>
#include <cstddef>

// ---------------- problem constants ----------------
#define NN     16384
#define DIN    1024
#define HH     4
#define CC     128
#define HC     512
#define EE     262144
#define ETOT   (EE + NN)
#define BB     16
#define NODES  1024
#define NBLK   64

// ---------------- device scratch ----------------
__device__ __half g_Hh[(size_t)NN * HC];     // GEMM output, fp16
__device__ __half g_Af[(size_t)NN * DIN];    // A operand (x, then h1)
__device__ __half g_Bf[DIN * HC];            // W operand
__device__ float  g_as[NN * HH];
__device__ float  g_ad[NN * HH];
__device__ int    g_src[ETOT];
__device__ int    g_dst[ETOT];
__device__ int    g_csrc[ETOT];
__device__ int    g_deg[NN];
__device__ int    g_cur[NN];
__device__ int    g_off[NN + 1];
__device__ int    g_bsum[NBLK];
__device__ int    g_is64;
__device__ float  g_x2[BB * NODES];
__device__ float  g_e1[BB * 512];
__device__ float  g_e2[BB * 256];
__device__ float  g_e3[BB * 128];
__device__ float  g_e4[BB * 64];

// ---------------- helpers ----------------
__device__ __forceinline__ float wsum(float v) {
#pragma unroll
    for (int o = 16; o > 0; o >>= 1) v += __shfl_xor_sync(0xffffffffu, v, o);
    return v;
}
__device__ __forceinline__ float wmax(float v) {
#pragma unroll
    for (int o = 16; o > 0; o >>= 1) v = fmaxf(v, __shfl_xor_sync(0xffffffffu, v, o));
    return v;
}
__device__ __forceinline__ float lrelu(float x) { return (x > 0.f) ? x : 0.2f * x; }
__device__ __forceinline__ void cp16(unsigned s, const void* g) {
    asm volatile("cp.async.cg.shared.global [%0], [%1], 16;" :: "r"(s), "l"(g));
}
__device__ __forceinline__ void ldsm4(unsigned* r, unsigned a) {
    asm volatile("ldmatrix.sync.aligned.m8n8.x4.shared.b16 {%0,%1,%2,%3}, [%4];"
                 : "=r"(r[0]), "=r"(r[1]), "=r"(r[2]), "=r"(r[3]) : "r"(a));
}
__device__ __forceinline__ void ldsm4t(unsigned* r, unsigned a) {
    asm volatile("ldmatrix.sync.aligned.m8n8.x4.trans.shared.b16 {%0,%1,%2,%3}, [%4];"
                 : "=r"(r[0]), "=r"(r[1]), "=r"(r[2]), "=r"(r[3]) : "r"(a));
}
__device__ __forceinline__ void mma16816(float* c, const unsigned* a, const unsigned* b) {
    asm volatile("mma.sync.aligned.m16n8k16.row.col.f32.f16.f16.f32 "
                 "{%0,%1,%2,%3}, {%4,%5,%6,%7}, {%8,%9}, {%0,%1,%2,%3};"
                 : "+f"(c[0]), "+f"(c[1]), "+f"(c[2]), "+f"(c[3])
                 : "r"(a[0]), "r"(a[1]), "r"(a[2]), "r"(a[3]), "r"(b[0]), "r"(b[1]));
}
__device__ __forceinline__ unsigned pack_h2(float a, float b) {
    __half2 t = __floats2half2_rn(a, b);
    return *(unsigned*)&t;
}

// ---------------- fp32 -> fp16 convert ----------------
__global__ void cvt_kernel(const float* __restrict__ x, __half* __restrict__ o) {
    const size_t i = (size_t)blockIdx.x * blockDim.x + threadIdx.x;
    const float4 v = ((const float4*)x)[i];
    ((uint2*)o)[i] = make_uint2(pack_h2(v.x, v.y), pack_h2(v.z, v.w));
}

// ---------------- fp16 tensor GEMM + fused alpha dots; fp16 C store ----------------
__global__ __launch_bounds__(256)
void gemm_fp16(const __half* __restrict__ A, const __half* __restrict__ B,
               __half* __restrict__ C, int M, int N, int K,
               const float* __restrict__ attS, const float* __restrict__ attD) {
    extern __shared__ __half sm[];
    __shared__ float s_att[2][128];
    __shared__ float sredS[2][128], sredD[2][128];
    const int tid   = threadIdx.x;
    const int mBase = blockIdx.y * 128;
    const int nBase = blockIdx.x * 128;
    const unsigned sbase = (unsigned)__cvta_generic_to_shared(sm);

    if (tid < 128) {
        s_att[0][tid] = attS[nBase + tid];
        s_att[1][tid] = attD[nBase + tid];
    }

    const int wid = tid >> 5, lane = tid & 31;
    const int wm = wid & 3;
    const int wn = wid >> 2;

    float acc[2][8][4];
#pragma unroll
    for (int i = 0; i < 2; i++)
#pragma unroll
        for (int j = 0; j < 8; j++)
#pragma unroll
            for (int k = 0; k < 4; k++) acc[i][j][k] = 0.f;

    auto load_stage = [&](int stage, int kt) {
        const int kb = kt * 32;
        const unsigned aBase = sbase + stage * 8192;
        const unsigned bBase = sbase + 32768 + stage * 8192;
#pragma unroll
        for (int i = 0; i < 2; i++) {
            const int chunk = tid + (i << 8);
            const int row = chunk >> 2, u = chunk & 3;
            const int su = u ^ ((row >> 1) & 3);
            cp16(aBase + row * 64 + su * 16, A + (size_t)(mBase + row) * K + kb + u * 8);
        }
#pragma unroll
        for (int i = 0; i < 2; i++) {
            const int chunk = tid + (i << 8);
            const int row = chunk >> 4, u = chunk & 15;
            const int su = u ^ (row & 7);
            cp16(bBase + row * 256 + su * 16, B + (size_t)(kb + row) * N + nBase + u * 8);
        }
    };

    const int nk = K >> 5;
    load_stage(0, 0);
    asm volatile("cp.async.commit_group;");
    load_stage(1, 1);
    asm volatile("cp.async.commit_group;");
    load_stage(2, 2);
    asm volatile("cp.async.commit_group;");

    for (int kt = 0; kt < nk; kt++) {
        if (kt + 3 < nk) load_stage((kt + 3) & 3, kt + 3);
        asm volatile("cp.async.commit_group;");
        asm volatile("cp.async.wait_group 3;");
        __syncthreads();

        const int stage = kt & 3;
        const unsigned aStage = sbase + stage * 8192;
        const unsigned bStage = sbase + 32768 + stage * 8192;
#pragma unroll
        for (int kk = 0; kk < 2; kk++) {
            unsigned ah[2][4], bh[4][4];
#pragma unroll
            for (int mt = 0; mt < 2; mt++) {
                const int row = wm * 32 + mt * 16 + (lane & 15);
                const int u = (kk * 2 + (lane >> 4)) ^ ((row >> 1) & 3);
                ldsm4(ah[mt], aStage + row * 64 + u * 16);
            }
#pragma unroll
            for (int nt = 0; nt < 4; nt++) {
                const int row = kk * 16 + (lane & 15);
                const int u = (wn * 8 + nt * 2 + (lane >> 4)) ^ (row & 7);
                ldsm4t(bh[nt], bStage + row * 256 + u * 16);
            }
#pragma unroll
            for (int mt = 0; mt < 2; mt++)
#pragma unroll
                for (int n8 = 0; n8 < 8; n8++)
                    mma16816(acc[mt][n8], ah[mt], &bh[n8 >> 1][(n8 & 1) * 2]);
        }
        __syncthreads();
    }

    // fp16 C store + fused alpha partials (alphas from fp32 accumulators)
    float psS[4] = {0.f, 0.f, 0.f, 0.f};
    float psD[4] = {0.f, 0.f, 0.f, 0.f};
#pragma unroll
    for (int mt = 0; mt < 2; mt++) {
#pragma unroll
        for (int n8 = 0; n8 < 8; n8++) {
            const int row0 = mBase + wm * 32 + mt * 16 + (lane >> 2);
            const int colL = wn * 64 + n8 * 8 + (lane & 3) * 2;
            *(unsigned*)&C[(size_t)row0 * N + nBase + colL]       = pack_h2(acc[mt][n8][0], acc[mt][n8][1]);
            *(unsigned*)&C[(size_t)(row0 + 8) * N + nBase + colL] = pack_h2(acc[mt][n8][2], acc[mt][n8][3]);
            const float aS0 = s_att[0][colL], aS1 = s_att[0][colL + 1];
            const float aD0 = s_att[1][colL], aD1 = s_att[1][colL + 1];
            psS[mt * 2 + 0] += acc[mt][n8][0] * aS0 + acc[mt][n8][1] * aS1;
            psS[mt * 2 + 1] += acc[mt][n8][2] * aS0 + acc[mt][n8][3] * aS1;
            psD[mt * 2 + 0] += acc[mt][n8][0] * aD0 + acc[mt][n8][1] * aD1;
            psD[mt * 2 + 1] += acc[mt][n8][2] * aD0 + acc[mt][n8][3] * aD1;
        }
    }
#pragma unroll
    for (int o = 1; o <= 2; o <<= 1) {
#pragma unroll
        for (int k = 0; k < 4; k++) {
            psS[k] += __shfl_xor_sync(0xffffffffu, psS[k], o);
            psD[k] += __shfl_xor_sync(0xffffffffu, psD[k], o);
        }
    }
    if ((lane & 3) == 0) {
        const int q = lane >> 2;
#pragma unroll
        for (int mt = 0; mt < 2; mt++) {
            sredS[wn][wm * 32 + mt * 16 + q]     = psS[mt * 2 + 0];
            sredS[wn][wm * 32 + mt * 16 + q + 8] = psS[mt * 2 + 1];
            sredD[wn][wm * 32 + mt * 16 + q]     = psD[mt * 2 + 0];
            sredD[wn][wm * 32 + mt * 16 + q + 8] = psD[mt * 2 + 1];
        }
    }
    __syncthreads();
    if (tid < 128) {
        const int row = mBase + tid;
        g_as[row * HH + blockIdx.x] = sredS[0][tid] + sredS[1][tid];
        g_ad[row * HH + blockIdx.x] = sredD[0][tid] + sredD[1][tid];
    }
}

// ---------------- CSR build ----------------
// detect + zero counts in one launch (grid NBLK, block 256)
__global__ void detect_zero(const int* __restrict__ buf) {
    const int i = blockIdx.x * 256 + threadIdx.x;
    if (i < NN) { g_deg[i] = 0; g_cur[i] = 0; }
    if (blockIdx.x == 0) {
        __shared__ int sh[256];
        int v = 0;
        for (int k = threadIdx.x; k < 8192; k += 256) v |= buf[2 * k + 1];
        sh[threadIdx.x] = v;
        __syncthreads();
        for (int s = 128; s > 0; s >>= 1) {
            if (threadIdx.x < s) sh[threadIdx.x] |= sh[threadIdx.x + s];
            __syncthreads();
        }
        if (threadIdx.x == 0) g_is64 = (sh[0] == 0) ? 1 : 0;
    }
}

__global__ void convert_kernel(const int* __restrict__ buf) {
    const int e = blockIdx.x * blockDim.x + threadIdx.x;
    if (e >= ETOT) return;
    int s, d;
    if (e >= EE) { s = d = e - EE; }
    else if (g_is64) { s = buf[2 * e]; d = buf[2 * (EE + e)]; }
    else             { s = buf[e];     d = buf[EE + e]; }
    g_src[e] = s; g_dst[e] = d;
    atomicAdd(&g_deg[d], 1);
}

__global__ void scan_blocks() {
    const int tid = threadIdx.x, lane = tid & 31, wid = tid >> 5;
    const int i = blockIdx.x * 256 + tid;
    const int v = g_deg[i];
    int x = v;
#pragma unroll
    for (int o = 1; o < 32; o <<= 1) {
        const int y = __shfl_up_sync(0xffffffffu, x, o);
        if (lane >= o) x += y;
    }
    __shared__ int ws[8], wsx[8];
    if (lane == 31) ws[wid] = x;
    __syncthreads();
    if (tid < 8) {
        int ex = 0;
        for (int k = 0; k < tid; k++) ex += ws[k];
        wsx[tid] = ex;
        if (tid == 7) g_bsum[blockIdx.x] = ex + ws[7];
    }
    __syncthreads();
    g_off[i] = wsx[wid] + (x - v);
}

__global__ void scan_bsum() {
    const int tid = threadIdx.x;
    const int v = g_bsum[tid];
    int x = v;
#pragma unroll
    for (int o = 1; o < 32; o <<= 1) {
        const int y = __shfl_up_sync(0xffffffffu, x, o);
        if ((tid & 31) >= o) x += y;
    }
    __shared__ int w0;
    if (tid == 31) w0 = x;
    __syncthreads();
    if (tid >= 32) x += w0;
    g_bsum[tid] = x - v;
    if (tid == 0) g_off[NN] = ETOT;
}

__global__ void scan_add() {
    const int i = blockIdx.x * 256 + threadIdx.x;
    g_off[i] += g_bsum[blockIdx.x];
}

__global__ void scatter_kernel() {
    const int e = blockIdx.x * blockDim.x + threadIdx.x;
    if (e >= ETOT) return;
    const int d = g_dst[e];
    const int pos = atomicAdd(&g_cur[d], 1);
    g_csrc[g_off[d] + pos] = g_src[e];
}

// ---------------- fused softmax + aggregate: warp per (node, head) ----------------
// pass 1: lanes parallel over edges -> online (M, S) from g_as gathers (4B/edge)
// pass 2: serial shfl gather of fp16 H rows, weights recomputed on the fly
// mode 0: elu(acc+bias) -> fp16 g_Af (layer 1 -> GEMM2 A operand)
// mode 1: dot(elu(acc+bias), p2w) -> red.add g_x2[n] (layer 2)
__global__ __launch_bounds__(256)
void csr_aggregate(const float* __restrict__ bias, const float* __restrict__ pw, int mode) {
    const int w = blockIdx.x * 8 + (threadIdx.x >> 5);
    const int lane = threadIdx.x & 31;
    const int n = w >> 2, h = w & 3;
    const int off0 = g_off[n];
    const int deg  = g_off[n + 1] - off0;
    const float ad_nh = g_ad[n * HH + h];

    // pass 1: softmax stats
    float m = -1e30f, s = 0.f;
    for (int j = lane; j < deg; j += 32) {
        const int src = g_csrc[off0 + j];
        const float x = lrelu(g_as[src * HH + h] + ad_nh);
        if (x > m) { s = s * __expf(m - x) + 1.f; m = x; } else s += __expf(x - m);
    }
    const float M = wmax(m);
    s *= __expf(m - M);
    const float S = wsum(s);
    const float invd = 1.f / (S + 1e-16f);

    // pass 2: gather (2-way unrolled, fp16 H)
    float4 acc = make_float4(0.f, 0.f, 0.f, 0.f);
    const __half* hbase = g_Hh + h * CC + lane * 4;
    for (int base = 0; base < deg; base += 32) {
        const int cnt = min(32, deg - base);
        int src = 0; float wgt = 0.f;
        if (lane < cnt) {
            src = g_csrc[off0 + base + lane];
            wgt = __expf(lrelu(g_as[src * HH + h] + ad_nh) - M) * invd;
        }
        int j = 0;
        for (; j + 1 < cnt; j += 2) {
            const int   s0 = __shfl_sync(0xffffffffu, src, j);
            const float w0 = __shfl_sync(0xffffffffu, wgt, j);
            const int   s1 = __shfl_sync(0xffffffffu, src, j + 1);
            const float w1 = __shfl_sync(0xffffffffu, wgt, j + 1);
            const uint2 p0 = *(const uint2*)(hbase + (size_t)s0 * HC);
            const uint2 p1 = *(const uint2*)(hbase + (size_t)s1 * HC);
            const float2 a0 = __half22float2(*(__half2*)&p0.x);
            const float2 b0 = __half22float2(*(__half2*)&p0.y);
            const float2 a1 = __half22float2(*(__half2*)&p1.x);
            const float2 b1 = __half22float2(*(__half2*)&p1.y);
            acc.x += a0.x * w0 + a1.x * w1;
            acc.y += a0.y * w0 + a1.y * w1;
            acc.z += b0.x * w0 + b1.x * w1;
            acc.w += b0.y * w0 + b1.y * w1;
        }
        if (j < cnt) {
            const int   s0 = __shfl_sync(0xffffffffu, src, j);
            const float w0 = __shfl_sync(0xffffffffu, wgt, j);
            const uint2 p0 = *(const uint2*)(hbase + (size_t)s0 * HC);
            const float2 a0 = __half22float2(*(__half2*)&p0.x);
            const float2 b0 = __half22float2(*(__half2*)&p0.y);
            acc.x += a0.x * w0; acc.y += a0.y * w0;
            acc.z += b0.x * w0; acc.w += b0.y * w0;
        }
    }

    const float4 b4 = *(const float4*)&bias[h * CC + lane * 4];
    float4 v = make_float4(acc.x + b4.x, acc.y + b4.y, acc.z + b4.z, acc.w + b4.w);
    v.x = (v.x > 0.f) ? v.x : expm1f(v.x);
    v.y = (v.y > 0.f) ? v.y : expm1f(v.y);
    v.z = (v.z > 0.f) ? v.z : expm1f(v.z);
    v.w = (v.w > 0.f) ? v.w : expm1f(v.w);
    if (mode == 0) {
        const size_t idx = (size_t)n * HC + h * CC + lane * 4;
        *(uint2*)&g_Af[idx] = make_uint2(pack_h2(v.x, v.y), pack_h2(v.z, v.w));
    } else {
        const float4 p = *(const float4*)&pw[h * CC + lane * 4];
        float dot = v.x * p.x + v.y * p.y + v.z * p.z + v.w * p.w;
        dot = wsum(dot);
        if (lane == 0)
            asm volatile("red.global.add.f32 [%0], %1;" :: "l"(&g_x2[n]), "f"(dot) : "memory");
    }
}

// ---------------- x2 init ----------------
__global__ void x2_init(const float* __restrict__ p2b) {
    const int i = blockIdx.x * blockDim.x + threadIdx.x;
    if (i < BB * NODES) g_x2[i] = p2b[0];
}

// ---------------- layer norm ----------------
__global__ void ln_kernel(const float* __restrict__ g, const float* __restrict__ be,
                          float* __restrict__ out) {
    const int bb = blockIdx.x, tid = threadIdx.x;
    const int lane = tid & 31, wid = tid >> 5;
    float s = 0.f, s2 = 0.f;
    for (int i = tid; i < NODES; i += 256) {
        const float v = g_x2[bb * NODES + i];
        s += v; s2 += v * v;
    }
    s = wsum(s); s2 = wsum(s2);
    __shared__ float shs[8], shs2[8];
    if (lane == 0) { shs[wid] = s; shs2[wid] = s2; }
    __syncthreads();
    __shared__ float smu, srv;
    if (tid == 0) {
        float S = 0.f, S2 = 0.f;
        for (int w = 0; w < 8; w++) { S += shs[w]; S2 += shs2[w]; }
        const float mu = S / NODES;
        smu = mu;
        srv = rsqrtf(S2 / NODES - mu * mu + 1e-5f);
    }
    __syncthreads();
    const float mu = smu, rv = srv;
    for (int i = tid; i < NODES; i += 256) {
        const float v = (g_x2[bb * NODES + i] - mu) * rv * g[i] + be[i];
        out[bb * NODES + i] = v;
        g_x2[bb * NODES + i] = v;
    }
}

// ---------------- small FC ----------------
__global__ void fc_kernel(const float* __restrict__ in, const float* __restrict__ W,
                          const float* __restrict__ bias, float* __restrict__ out,
                          int Din, int Dout, int act) {
    const int j = blockIdx.x * blockDim.x + threadIdx.x;
    const int b = blockIdx.y;
    if (j >= Dout) return;
    const float* ir = in + (size_t)b * Din;
    float s = bias[j];
    for (int k = 0; k < Din; k++) s += ir[k] * W[(size_t)k * Dout + j];
    if (act) s = (s > 0.f) ? s : expm1f(s);
    out[b * Dout + j] = s;
}

// ---------------- final ----------------
__global__ void final_kernel(const float* __restrict__ lw, const float* __restrict__ lb,
                             float* __restrict__ out) {
    const int b = blockIdx.x, tid = threadIdx.x;
    const float v = g_e4[b * 64 + tid];
    out[BB * NODES + b * 64 + tid] = v;
    float p = v * lw[tid];
#pragma unroll
    for (int o = 16; o > 0; o >>= 1) p += __shfl_xor_sync(0xffffffffu, p, o);
    __shared__ float sh[2];
    if ((tid & 31) == 0) sh[tid >> 5] = p;
    __syncthreads();
    if (tid == 0) out[BB * NODES + BB * 64 + b] = sh[0] + sh[1] + lb[0];
}

// ---------------- launch ----------------
extern "C" void kernel_launch(void* const* d_in, const int* in_sizes, int n_in,
                              void* d_out, int out_size) {
    const float* x     = (const float*)d_in[0];
    const int*   eibuf = (const int*)d_in[1];
    const float* W1   = (const float*)d_in[3];
    const float* as1  = (const float*)d_in[4];
    const float* ad1  = (const float*)d_in[5];
    const float* b1   = (const float*)d_in[6];
    const float* W2   = (const float*)d_in[7];
    const float* as2  = (const float*)d_in[8];
    const float* ad2  = (const float*)d_in[9];
    const float* b2   = (const float*)d_in[10];
    const float* p2w  = (const float*)d_in[13];
    const float* p2b  = (const float*)d_in[14];
    const float* ln_g = (const float*)d_in[15];
    const float* ln_b = (const float*)d_in[16];
    const float* fw1  = (const float*)d_in[17];
    const float* fb1  = (const float*)d_in[18];
    const float* fw2  = (const float*)d_in[19];
    const float* fb2  = (const float*)d_in[20];
    const float* fw3  = (const float*)d_in[21];
    const float* fb3  = (const float*)d_in[22];
    const float* fw4  = (const float*)d_in[23];
    const float* fb4  = (const float*)d_in[24];
    const float* lw   = (const float*)d_in[25];
    const float* lb   = (const float*)d_in[26];
    float* out = (float*)d_out;

    float *px2, *pe1, *pe2, *pe3, *pe4;
    __half *pHh, *pAf, *pBf;
    cudaGetSymbolAddress((void**)&pHh, g_Hh);
    cudaGetSymbolAddress((void**)&pAf, g_Af);
    cudaGetSymbolAddress((void**)&pBf, g_Bf);
    cudaGetSymbolAddress((void**)&px2, g_x2);
    cudaGetSymbolAddress((void**)&pe1, g_e1);
    cudaGetSymbolAddress((void**)&pe2, g_e2);
    cudaGetSymbolAddress((void**)&pe3, g_e3);
    cudaGetSymbolAddress((void**)&pe4, g_e4);

    cudaFuncSetAttribute(gemm_fp16, cudaFuncAttributeMaxDynamicSharedMemorySize, 65536);

    const int eblocks = (ETOT + 255) / 256;
    const dim3 gemm_grid(HC / 128, NN / 128);

    // launch order: gemm_fp16 (layer 1) is launch index 5 for ncu -s 5
    cvt_kernel<<<(NN * DIN / 4) / 256, 256>>>(x, pAf);                          // 0
    cvt_kernel<<<(DIN * HC / 4) / 256, 256>>>(W1, pBf);                         // 1
    detect_zero<<<NBLK, 256>>>(eibuf);                                          // 2
    convert_kernel<<<eblocks, 256>>>(eibuf);                                    // 3
    scan_blocks<<<NBLK, 256>>>();                                               // 4
    gemm_fp16<<<gemm_grid, 256, 65536>>>(pAf, pBf, pHh, NN, HC, DIN, as1, ad1); // 5
    scan_bsum<<<1, 64>>>();
    scan_add<<<NBLK, 256>>>();
    scatter_kernel<<<eblocks, 256>>>();
    csr_aggregate<<<NN * HH / 8, 256>>>(b1, nullptr, 0);   // fused softmax+gather -> fp16 h1

    // ===== GAT layer 2 =====
    cvt_kernel<<<(HC * HC / 4) / 256, 256>>>(W2, pBf);
    gemm_fp16<<<gemm_grid, 256, 65536>>>(pAf, pBf, pHh, NN, HC, HC, as2, ad2);
    x2_init<<<(BB * NODES) / 256, 256>>>(p2b);
    csr_aggregate<<<NN * HH / 8, 256>>>(b2, p2w, 1);       // fused pool -> g_x2

    // ===== layer norm -> d_out[0:16384) =====
    ln_kernel<<<BB, 256>>>(ln_g, ln_b, out);

    // ===== encoder MLP =====
    fc_kernel<<<dim3(4, BB), 128>>>(px2, fw1, fb1, pe1, 1024, 512, 1);
    fc_kernel<<<dim3(2, BB), 128>>>(pe1, fw2, fb2, pe2, 512, 256, 1);
    fc_kernel<<<dim3(1, BB), 128>>>(pe2, fw3, fb3, pe3, 256, 128, 1);
    fc_kernel<<<dim3(1, BB), 128>>>(pe3, fw4, fb4, pe4, 128, 64, 1);
    final_kernel<<<BB, 64>>>(lw, lb, out);
}